// round 7
// baseline (speedup 1.0000x reference)
#include <cuda_runtime.h>
#include <math.h>

#define VOCAB 32000
#define EMB   32
#define HID   8
#define SEQ   64
#define BATCH 64
#define NROWS (SEQ*BATCH)   /* 4096 */

typedef unsigned long long u64;

__device__ __forceinline__ u64 ffma2(u64 a, u64 b, u64 c) {
    u64 d; asm("fma.rn.f32x2 %0, %1, %2, %3;" : "=l"(d) : "l"(a), "l"(b), "l"(c)); return d;
}
__device__ __forceinline__ u64 fadd2(u64 a, u64 b) {
    u64 d; asm("add.rn.f32x2 %0, %1, %2;" : "=l"(d) : "l"(a), "l"(b)); return d;
}
__device__ __forceinline__ u64 pack2(float x, float y) {
    u64 d; asm("mov.b64 %0, {%1, %2};" : "=l"(d) : "r"(__float_as_uint(x)), "r"(__float_as_uint(y))); return d;
}
__device__ __forceinline__ void unpack2(u64 v, float& x, float& y) {
    unsigned a, b; asm("mov.b64 {%0, %1}, %2;" : "=r"(a), "=r"(b) : "l"(v));
    x = __uint_as_float(a); y = __uint_as_float(b);
}
__device__ __forceinline__ float tanh_fast(float x) {
    float y; asm("tanh.approx.f32 %0, %1;" : "=f"(y) : "f"(x)); return y;
}

// Scratch (device globals: allocation-free rule)
__device__ float g_A[2*SEQ*BATCH*10];
__device__ float g_h[NROWS*16];
__device__ float g_sum[NROWS];

// ---------------------------------------------------------------------------
// Kernel 0: embedding gather + input-projection precompute
// ---------------------------------------------------------------------------
__global__ __launch_bounds__(64) void k_pre(
    const int*   __restrict__ x,   const float* __restrict__ emb,
    const float* __restrict__ Wz1, const float* __restrict__ bz1,
    const float* __restrict__ Wr1, const float* __restrict__ br1,
    const float* __restrict__ Wh1, const float* __restrict__ bh1,
    const float* __restrict__ Wz2, const float* __restrict__ bz2,
    const float* __restrict__ Wr2, const float* __restrict__ br2,
    const float* __restrict__ Wh2, const float* __restrict__ bh2)
{
    int t = blockIdx.x, dir = blockIdx.y, b = threadIdx.x;
    int gid = (dir*SEQ + t)*BATCH + b;
    if (gid < NROWS) g_sum[gid] = 0.f;

    const float* Wz = dir ? Wz2 : Wz1;
    const float* Wr = dir ? Wr2 : Wr1;
    const float* Wh = dir ? Wh2 : Wh1;
    float az = (dir ? bz2 : bz1)[0];
    float ar = (dir ? br2 : br1)[0];
    const float* bh = dir ? bh2 : bh1;
    float ah[8];
    #pragma unroll
    for (int j = 0; j < 8; j++) ah[j] = bh[j];

    int idx = x[t*BATCH + b];
    const float* e = emb + (size_t)idx * EMB;
    float ev[32];
    #pragma unroll
    for (int k = 0; k < 8; k++) {
        float4 v4 = ((const float4*)e)[k];
        ev[4*k+0] = v4.x; ev[4*k+1] = v4.y; ev[4*k+2] = v4.z; ev[4*k+3] = v4.w;
    }
    #pragma unroll
    for (int k = 0; k < 32; k++) {
        float evk = ev[k];
        az += evk * Wz[8 + k];
        ar += evk * Wr[8 + k];
        #pragma unroll
        for (int j = 0; j < 8; j++) ah[j] += evk * Wh[(8 + k)*8 + j];
    }
    float* Ab = g_A + (size_t)((dir*SEQ + t)*10)*BATCH + b;
    Ab[0] = az;
    Ab[BATCH] = ar;
    #pragma unroll
    for (int j = 0; j < 8; j++) Ab[(2 + j)*BATCH] = ah[j];
}

// ---------------------------------------------------------------------------
// Kernel 1: serial GRU, 2 dirs x 64 batches.
// ---------------------------------------------------------------------------
__global__ __launch_bounds__(128) void k_gru(
    const float* __restrict__ Wz1, const float* __restrict__ Wr1, const float* __restrict__ Wh1,
    const float* __restrict__ Wz2, const float* __restrict__ Wr2, const float* __restrict__ Wh2)
{
    int tid = threadIdx.x;
    int dir = tid >> 6, b = tid & 63;
    const float* Wz = dir ? Wz2 : Wz1;
    const float* Wr = dir ? Wr2 : Wr1;
    const float* Wh = dir ? Wh2 : Wh1;

    float wz[8], wr[8], wh[64];
    #pragma unroll
    for (int i = 0; i < 8; i++) { wz[i] = Wz[i]; wr[i] = Wr[i]; }
    #pragma unroll
    for (int i = 0; i < 64; i++) wh[i] = Wh[i];

    float h[8];
    #pragma unroll
    for (int j = 0; j < 8; j++) h[j] = 0.f;

    for (int step = 0; step < SEQ; ++step) {
        int time = dir ? (SEQ - 1 - step) : step;

        float* gh = g_h + (size_t)(time*BATCH + b)*16 + dir*8;
        ((float4*)gh)[0] = make_float4(h[0], h[1], h[2], h[3]);
        ((float4*)gh)[1] = make_float4(h[4], h[5], h[6], h[7]);

        const float* A = g_A + (size_t)((dir*SEQ + time)*10)*BATCH + b;
        float zi = A[0], ri = A[BATCH];
        #pragma unroll
        for (int i = 0; i < 8; i++) { zi += h[i]*wz[i]; ri += h[i]*wr[i]; }
        float z = 1.f / (1.f + __expf(-zi));
        float r = 1.f / (1.f + __expf(-ri));
        float hc[8];
        #pragma unroll
        for (int j = 0; j < 8; j++) {
            float s = A[(2 + j)*BATCH];
            #pragma unroll
            for (int i = 0; i < 8; i++) s += (r*h[i]) * wh[i*8 + j];
            hc[j] = tanh_fast(s);
        }
        #pragma unroll
        for (int j = 0; j < 8; j++) h[j] += z * (hc[j] - h[j]);
    }
}

// ---------------------------------------------------------------------------
// Shared mainloop shape for passes 2a/2b:
// Block = 64 rows x 1280 v (5 iters of 256 v). Warp owns 8 rows; lane owns
// 8 consecutive v (2 float4 spans). One h-pair LDS.128 feeds 8 FFMA2
// (was 4) -> smem traffic halved vs previous rounds.
// Per v-iter/thread: 32 LDG.128 + 64 LDS.128 + 512 FFMA2.
// ---------------------------------------------------------------------------
#define MAINLOOP_ACC(OUT_KK)                                                  \
    ulonglong2 w0a = *(const ulonglong2*)(Wp);                                \
    ulonglong2 w0b = *(const ulonglong2*)(Wp + 4);                            \
    ulonglong2 w1a = *(const ulonglong2*)(Wp + VOCAB);                        \
    ulonglong2 w1b = *(const ulonglong2*)(Wp + VOCAB + 4);                    \
    _Pragma("unroll")                                                         \
    for (int r = 0; r < 8; r++) {                                             \
        ulonglong2 h01 = *(const ulonglong2*)(hp + r*16 + (OUT_KK));          \
        a0[r] = ffma2(w0a.x, h01.x, a0[r]);                                   \
        a1[r] = ffma2(w0a.y, h01.x, a1[r]);                                   \
        a2[r] = ffma2(w0b.x, h01.x, a2[r]);                                   \
        a3[r] = ffma2(w0b.y, h01.x, a3[r]);                                   \
        a0[r] = ffma2(w1a.x, h01.y, a0[r]);                                   \
        a1[r] = ffma2(w1a.y, h01.y, a1[r]);                                   \
        a2[r] = ffma2(w1b.x, h01.y, a2[r]);                                   \
        a3[r] = ffma2(w1b.y, h01.y, a3[r]);                                   \
    }

__global__ __launch_bounds__(256, 2) void k_sumexp(
    const float* __restrict__ Wout, const float* __restrict__ bout)
{
    __shared__ __align__(16) u64 h_pack[64*16];
    int tid = threadIdx.x;
    int by  = blockIdx.y;                 // rows by*64 .. by*64+63
    for (int i = tid; i < 64*16; i += 256) {
        float v = g_h[(size_t)by*1024 + i];
        h_pack[i] = pack2(v, v);
    }
    __syncthreads();

    int warp = tid >> 5, lane = tid & 31;
    const u64* hp = h_pack + warp*8*16;
    float part[8];
    #pragma unroll
    for (int r = 0; r < 8; r++) part[r] = 0.f;

    int vbase = blockIdx.x*1280 + lane*8;
    #pragma unroll 1
    for (int it = 0; it < 5; ++it) {
        int v = vbase + it*256;
        ulonglong2 ba = *(const ulonglong2*)(bout + v);
        ulonglong2 bb = *(const ulonglong2*)(bout + v + 4);
        u64 a0[8], a1[8], a2[8], a3[8];
        #pragma unroll
        for (int r = 0; r < 8; r++) { a0[r]=ba.x; a1[r]=ba.y; a2[r]=bb.x; a3[r]=bb.y; }
        #pragma unroll
        for (int kk = 0; kk < 16; kk += 2) {
            const float* Wp = Wout + (size_t)kk*VOCAB + v;
            MAINLOOP_ACC(kk)
        }
        #pragma unroll
        for (int r = 0; r < 8; r++) {
            float e0,e1,e2,e3,e4,e5,e6,e7;
            unpack2(a0[r], e0, e1);
            unpack2(a1[r], e2, e3);
            unpack2(a2[r], e4, e5);
            unpack2(a3[r], e6, e7);
            part[r] += ((__expf(e0)+__expf(e1)) + (__expf(e2)+__expf(e3)))
                     + ((__expf(e4)+__expf(e5)) + (__expf(e6)+__expf(e7)));
        }
    }
    #pragma unroll
    for (int r = 0; r < 8; r++) {
        float p = part[r];
        #pragma unroll
        for (int off = 16; off > 0; off >>= 1)
            p += __shfl_xor_sync(0xffffffffu, p, off);
        if (lane == 0) atomicAdd(&g_sum[by*64 + warp*8 + r], p);
    }
}

__global__ __launch_bounds__(256, 2) void k_write(
    const float* __restrict__ Wout, const float* __restrict__ bout,
    float* __restrict__ out)
{
    __shared__ __align__(16) u64 h_pack[64*16];
    __shared__ u64 nls_sh[64];
    int tid = threadIdx.x;
    int by  = blockIdx.y;
    for (int i = tid; i < 64*16; i += 256) {
        float v = g_h[(size_t)by*1024 + i];
        h_pack[i] = pack2(v, v);
    }
    if (tid < 64) {
        float nls = -__logf(g_sum[by*64 + tid]);
        nls_sh[tid] = pack2(nls, nls);
    }
    __syncthreads();

    int warp = tid >> 5, lane = tid & 31;
    const u64* hp = h_pack + warp*8*16;
    u64 nls[8];
    #pragma unroll
    for (int r = 0; r < 8; r++) nls[r] = nls_sh[warp*8 + r];

    int row_base = by*64 + warp*8;
    int vbase = blockIdx.x*1280 + lane*8;
    #pragma unroll 1
    for (int it = 0; it < 5; ++it) {
        int v = vbase + it*256;
        ulonglong2 ba = *(const ulonglong2*)(bout + v);
        ulonglong2 bb = *(const ulonglong2*)(bout + v + 4);
        u64 a0[8], a1[8], a2[8], a3[8];
        #pragma unroll
        for (int r = 0; r < 8; r++) { a0[r]=ba.x; a1[r]=ba.y; a2[r]=bb.x; a3[r]=bb.y; }
        #pragma unroll
        for (int kk = 0; kk < 16; kk += 2) {
            const float* Wp = Wout + (size_t)kk*VOCAB + v;
            MAINLOOP_ACC(kk)
        }
        #pragma unroll
        for (int r = 0; r < 8; r++) {
            u64 o0 = fadd2(a0[r], nls[r]);
            u64 o1 = fadd2(a1[r], nls[r]);
            u64 o2 = fadd2(a2[r], nls[r]);
            u64 o3 = fadd2(a3[r], nls[r]);
            float* p = out + (size_t)(row_base + r)*VOCAB + v;
            asm volatile("st.global.cs.v2.u64 [%0], {%1, %2};"
                         :: "l"(p), "l"(o0), "l"(o1) : "memory");
            asm volatile("st.global.cs.v2.u64 [%0], {%1, %2};"
                         :: "l"(p + 4), "l"(o2), "l"(o3) : "memory");
        }
    }
}

// ---------------------------------------------------------------------------
extern "C" void kernel_launch(void* const* d_in, const int* in_sizes, int n_in,
                              void* d_out, int out_size)
{
    const int*   x    = (const int*)  d_in[0];
    const float* emb  = (const float*)d_in[1];
    const float* Wz1  = (const float*)d_in[2];  const float* bz1 = (const float*)d_in[3];
    const float* Wr1  = (const float*)d_in[4];  const float* br1 = (const float*)d_in[5];
    const float* Wh1  = (const float*)d_in[6];  const float* bh1 = (const float*)d_in[7];
    const float* Wz2  = (const float*)d_in[8];  const float* bz2 = (const float*)d_in[9];
    const float* Wr2  = (const float*)d_in[10]; const float* br2 = (const float*)d_in[11];
    const float* Wh2  = (const float*)d_in[12]; const float* bh2 = (const float*)d_in[13];
    const float* Wout = (const float*)d_in[14]; const float* bout= (const float*)d_in[15];
    float* out = (float*)d_out;

    k_pre<<<dim3(SEQ, 2), BATCH>>>(x, emb, Wz1, bz1, Wr1, br1, Wh1, bh1,
                                   Wz2, bz2, Wr2, br2, Wh2, bh2);
    k_gru<<<1, 128>>>(Wz1, Wr1, Wh1, Wz2, Wr2, Wh2);
    k_sumexp<<<dim3(25, 64), 256>>>(Wout, bout);
    k_write <<<dim3(25, 64), 256>>>(Wout, bout, out);
}

// round 8
// speedup vs baseline: 1.4641x; 1.4641x over previous
#include <cuda_runtime.h>
#include <math.h>

#define VOCAB 32000
#define EMB   32
#define HID   8
#define SEQ   64
#define BATCH 64
#define NROWS (SEQ*BATCH)   /* 4096 */

typedef unsigned long long u64;

__device__ __forceinline__ u64 ffma2(u64 a, u64 b, u64 c) {
    u64 d; asm("fma.rn.f32x2 %0, %1, %2, %3;" : "=l"(d) : "l"(a), "l"(b), "l"(c)); return d;
}
__device__ __forceinline__ u64 fadd2(u64 a, u64 b) {
    u64 d; asm("add.rn.f32x2 %0, %1, %2;" : "=l"(d) : "l"(a), "l"(b)); return d;
}
__device__ __forceinline__ u64 pack2(float x, float y) {
    u64 d; asm("mov.b64 %0, {%1, %2};" : "=l"(d) : "r"(__float_as_uint(x)), "r"(__float_as_uint(y))); return d;
}
__device__ __forceinline__ float tanh_fast(float x) {
    float y; asm("tanh.approx.f32 %0, %1;" : "=f"(y) : "f"(x)); return y;
}

// Scratch (device globals: allocation-free rule)
__device__ float g_A[2*SEQ*BATCH*10];
__device__ float g_h[NROWS*16];
__device__ float g_sum[NROWS];

// ---------------------------------------------------------------------------
// Kernel 0: embedding gather + input-projection precompute (R1 form)
// ---------------------------------------------------------------------------
__global__ __launch_bounds__(64) void k_pre(
    const int*   __restrict__ x,   const float* __restrict__ emb,
    const float* __restrict__ Wz1, const float* __restrict__ bz1,
    const float* __restrict__ Wr1, const float* __restrict__ br1,
    const float* __restrict__ Wh1, const float* __restrict__ bh1,
    const float* __restrict__ Wz2, const float* __restrict__ bz2,
    const float* __restrict__ Wr2, const float* __restrict__ br2,
    const float* __restrict__ Wh2, const float* __restrict__ bh2)
{
    int t = blockIdx.x, dir = blockIdx.y, b = threadIdx.x;
    int gid = (dir*SEQ + t)*BATCH + b;
    if (gid < NROWS) g_sum[gid] = 0.f;

    const float* Wz = dir ? Wz2 : Wz1;
    const float* Wr = dir ? Wr2 : Wr1;
    const float* Wh = dir ? Wh2 : Wh1;
    float az = (dir ? bz2 : bz1)[0];
    float ar = (dir ? br2 : br1)[0];
    const float* bh = dir ? bh2 : bh1;
    float ah[8];
    #pragma unroll
    for (int j = 0; j < 8; j++) ah[j] = bh[j];

    int idx = x[t*BATCH + b];
    const float* e = emb + (size_t)idx * EMB;
    float ev[32];
    #pragma unroll
    for (int k = 0; k < 8; k++) {
        float4 v4 = ((const float4*)e)[k];
        ev[4*k+0] = v4.x; ev[4*k+1] = v4.y; ev[4*k+2] = v4.z; ev[4*k+3] = v4.w;
    }
    #pragma unroll
    for (int k = 0; k < 32; k++) {
        float evk = ev[k];
        az += evk * Wz[8 + k];
        ar += evk * Wr[8 + k];
        #pragma unroll
        for (int j = 0; j < 8; j++) ah[j] += evk * Wh[(8 + k)*8 + j];
    }
    float* Ab = g_A + (size_t)((dir*SEQ + t)*10)*BATCH + b;
    Ab[0] = az;
    Ab[BATCH] = ar;
    #pragma unroll
    for (int j = 0; j < 8; j++) Ab[(2 + j)*BATCH] = ah[j];
}

// ---------------------------------------------------------------------------
// Kernel 1: serial GRU (R1 form), 2 dirs x 64 batches.
// ---------------------------------------------------------------------------
__global__ __launch_bounds__(128) void k_gru(
    const float* __restrict__ Wz1, const float* __restrict__ Wr1, const float* __restrict__ Wh1,
    const float* __restrict__ Wz2, const float* __restrict__ Wr2, const float* __restrict__ Wh2)
{
    int tid = threadIdx.x;
    int dir = tid >> 6, b = tid & 63;
    const float* Wz = dir ? Wz2 : Wz1;
    const float* Wr = dir ? Wr2 : Wr1;
    const float* Wh = dir ? Wh2 : Wh1;

    float wz[8], wr[8], wh[64];
    #pragma unroll
    for (int i = 0; i < 8; i++) { wz[i] = Wz[i]; wr[i] = Wr[i]; }
    #pragma unroll
    for (int i = 0; i < 64; i++) wh[i] = Wh[i];

    float h[8];
    #pragma unroll
    for (int j = 0; j < 8; j++) h[j] = 0.f;

    for (int step = 0; step < SEQ; ++step) {
        int time = dir ? (SEQ - 1 - step) : step;

        float* gh = g_h + (size_t)(time*BATCH + b)*16 + dir*8;
        ((float4*)gh)[0] = make_float4(h[0], h[1], h[2], h[3]);
        ((float4*)gh)[1] = make_float4(h[4], h[5], h[6], h[7]);

        const float* A = g_A + (size_t)((dir*SEQ + time)*10)*BATCH + b;
        float zi = A[0], ri = A[BATCH];
        #pragma unroll
        for (int i = 0; i < 8; i++) { zi += h[i]*wz[i]; ri += h[i]*wr[i]; }
        float z = 1.f / (1.f + __expf(-zi));
        float r = 1.f / (1.f + __expf(-ri));
        float hc[8];
        #pragma unroll
        for (int j = 0; j < 8; j++) {
            float s = A[(2 + j)*BATCH];
            #pragma unroll
            for (int i = 0; i < 8; i++) s += (r*h[i]) * wh[i*8 + j];
            hc[j] = tanh_fast(s);
        }
        #pragma unroll
        for (int j = 0; j < 8; j++) h[j] += z * (hc[j] - h[j]);
    }
}

// ---------------------------------------------------------------------------
// Kernel 2a: sumexp pass — R1 SCALAR form exactly (best measured variant).
// Block = 64 rows x 1280 v; warp owns 8 rows; thread owns 4 v (float4).
// Uncapped registers.
// ---------------------------------------------------------------------------
__global__ __launch_bounds__(256) void k_sumexp(
    const float* __restrict__ Wout, const float* __restrict__ bout)
{
    __shared__ float h_sh[64*16];
    int tid = threadIdx.x;
    int by  = blockIdx.y;
    ((float4*)h_sh)[tid] = ((const float4*)(g_h + (size_t)by*64*16))[tid];
    __syncthreads();

    int warp = tid >> 5, lane = tid & 31;
    const float* hrow = h_sh + warp*8*16;
    float part[8];
    #pragma unroll
    for (int r = 0; r < 8; r++) part[r] = 0.f;

    int vbase = blockIdx.x*1280 + lane*4;
    for (int it = 0; it < 10; ++it) {
        int v = vbase + it*128;
        float4 bo = *(const float4*)(bout + v);
        float4 acc[8];
        #pragma unroll
        for (int r = 0; r < 8; r++) acc[r] = bo;
        #pragma unroll
        for (int k = 0; k < 16; k++) {
            float4 wv = *(const float4*)(Wout + (size_t)k*VOCAB + v);
            #pragma unroll
            for (int r = 0; r < 8; r++) {
                float hk = hrow[r*16 + k];
                acc[r].x = fmaf(hk, wv.x, acc[r].x);
                acc[r].y = fmaf(hk, wv.y, acc[r].y);
                acc[r].z = fmaf(hk, wv.z, acc[r].z);
                acc[r].w = fmaf(hk, wv.w, acc[r].w);
            }
        }
        #pragma unroll
        for (int r = 0; r < 8; r++) {
            part[r] += __expf(acc[r].x) + __expf(acc[r].y)
                     + __expf(acc[r].z) + __expf(acc[r].w);
        }
    }
    #pragma unroll
    for (int r = 0; r < 8; r++) {
        float p = part[r];
        #pragma unroll
        for (int off = 16; off > 0; off >>= 1)
            p += __shfl_xor_sync(0xffffffffu, p, off);
        if (lane == 0) atomicAdd(&g_sum[by*64 + warp*8 + r], p);
    }
}

// ---------------------------------------------------------------------------
// Kernel 2b: write pass — R4 FFMA2 form exactly (131us, measured 3x).
// ---------------------------------------------------------------------------
__global__ __launch_bounds__(256, 2) void k_write(
    const float* __restrict__ Wout, const float* __restrict__ bout,
    float* __restrict__ out)
{
    __shared__ __align__(16) u64 h_pack[64*16];
    __shared__ u64 nls_sh[64];
    int tid = threadIdx.x;
    int by  = blockIdx.y;
    for (int i = tid; i < 64*16; i += 256) {
        float v = g_h[(size_t)by*1024 + i];
        h_pack[i] = pack2(v, v);
    }
    if (tid < 64) {
        float nls = -__logf(g_sum[by*64 + tid]);
        nls_sh[tid] = pack2(nls, nls);
    }
    __syncthreads();

    int warp = tid >> 5, lane = tid & 31;
    const u64* hp = h_pack + warp*8*16;
    u64 nls[8];
    #pragma unroll
    for (int r = 0; r < 8; r++) nls[r] = nls_sh[warp*8 + r];

    int row_base = by*64 + warp*8;
    int vbase = blockIdx.x*1280 + lane*4;
    #pragma unroll 1
    for (int it = 0; it < 10; ++it) {
        int v = vbase + it*128;
        ulonglong2 bo = *(const ulonglong2*)(bout + v);
        u64 a0[8], a1[8];
        #pragma unroll
        for (int r = 0; r < 8; r++) { a0[r] = bo.x; a1[r] = bo.y; }
        #pragma unroll
        for (int kk = 0; kk < 16; kk += 2) {
            ulonglong2 w0 = *(const ulonglong2*)(Wout + (size_t)kk*VOCAB + v);
            ulonglong2 w1 = *(const ulonglong2*)(Wout + (size_t)(kk+1)*VOCAB + v);
            #pragma unroll
            for (int r = 0; r < 8; r++) {
                ulonglong2 h01 = *(const ulonglong2*)(hp + r*16 + kk);
                a0[r] = ffma2(w0.x, h01.x, a0[r]);
                a1[r] = ffma2(w0.y, h01.x, a1[r]);
                a0[r] = ffma2(w1.x, h01.y, a0[r]);
                a1[r] = ffma2(w1.y, h01.y, a1[r]);
            }
        }
        #pragma unroll
        for (int r = 0; r < 8; r++) {
            u64 o0 = fadd2(a0[r], nls[r]);
            u64 o1 = fadd2(a1[r], nls[r]);
            float* p = out + (size_t)(row_base + r)*VOCAB + v;
            asm volatile("st.global.cs.v2.u64 [%0], {%1, %2};"
                         :: "l"(p), "l"(o0), "l"(o1) : "memory");
        }
    }
}

// ---------------------------------------------------------------------------
extern "C" void kernel_launch(void* const* d_in, const int* in_sizes, int n_in,
                              void* d_out, int out_size)
{
    const int*   x    = (const int*)  d_in[0];
    const float* emb  = (const float*)d_in[1];
    const float* Wz1  = (const float*)d_in[2];  const float* bz1 = (const float*)d_in[3];
    const float* Wr1  = (const float*)d_in[4];  const float* br1 = (const float*)d_in[5];
    const float* Wh1  = (const float*)d_in[6];  const float* bh1 = (const float*)d_in[7];
    const float* Wz2  = (const float*)d_in[8];  const float* bz2 = (const float*)d_in[9];
    const float* Wr2  = (const float*)d_in[10]; const float* br2 = (const float*)d_in[11];
    const float* Wh2  = (const float*)d_in[12]; const float* bh2 = (const float*)d_in[13];
    const float* Wout = (const float*)d_in[14]; const float* bout= (const float*)d_in[15];
    float* out = (float*)d_out;

    k_pre<<<dim3(SEQ, 2), BATCH>>>(x, emb, Wz1, bz1, Wr1, br1, Wh1, bh1,
                                   Wz2, bz2, Wr2, br2, Wh2, bh2);
    k_gru<<<1, 128>>>(Wz1, Wr1, Wh1, Wz2, Wr2, Wh2);
    k_sumexp<<<dim3(25, 64), 256>>>(Wout, bout);
    k_write <<<dim3(25, 64), 256>>>(Wout, bout, out);
}

// round 10
// speedup vs baseline: 2.0272x; 1.3846x over previous
#include <cuda_runtime.h>
#include <cuda_bf16.h>
#include <math.h>

#define VOCAB 32000
#define EMB   32
#define HID   8
#define SEQ   64
#define BATCH 64
#define NROWS (SEQ*BATCH)   /* 4096 */
#define NTILES (VOCAB/8)    /* 4000 n8 tiles */

typedef unsigned long long u64;

__device__ float g_A[2*SEQ*BATCH*10];
__device__ float g_h[NROWS*16];
__device__ float g_sum[NROWS];
// B fragments: per n8-tile: [hi j-pairs interleaved 64 u32][lo 64 u32] = 128 u32
__device__ unsigned g_Bw[NTILES*128];    // 2 MB

__device__ __forceinline__ float tanh_fast(float x) {
    float y; asm("tanh.approx.f32 %0, %1;" : "=f"(y) : "f"(x)); return y;
}

// split a float2 into packed bf16x2 hi and lo words (x in low half)
__device__ __forceinline__ void split2(float2 v, unsigned& hi, unsigned& lo) {
    __nv_bfloat16 hx = __float2bfloat16(v.x);
    __nv_bfloat16 hy = __float2bfloat16(v.y);
    __nv_bfloat16 lx = __float2bfloat16(v.x - __bfloat162float(hx));
    __nv_bfloat16 ly = __float2bfloat16(v.y - __bfloat162float(hy));
    hi = (unsigned)__bfloat16_as_ushort(hx) | ((unsigned)__bfloat16_as_ushort(hy) << 16);
    lo = (unsigned)__bfloat16_as_ushort(lx) | ((unsigned)__bfloat16_as_ushort(ly) << 16);
}

__device__ __forceinline__ void mma_bf16(
    float& c0, float& c1, float& c2, float& c3,
    unsigned a0, unsigned a1, unsigned a2, unsigned a3,
    unsigned b0, unsigned b1)
{
    asm volatile(
        "mma.sync.aligned.m16n8k16.row.col.f32.bf16.bf16.f32 "
        "{%0,%1,%2,%3}, {%4,%5,%6,%7}, {%8,%9}, {%0,%1,%2,%3};"
        : "+f"(c0), "+f"(c1), "+f"(c2), "+f"(c3)
        : "r"(a0), "r"(a1), "r"(a2), "r"(a3), "r"(b0), "r"(b1));
}

// Build A fragments (hi and lo) for rows r0, r0+8; q = lane%4.
// m16n8k16 A layout: a0:(row g, k 2q..2q+1) a1:(row g+8, same) a2:(row g, k+8) a3:(row g+8, k+8)
__device__ __forceinline__ void build_a(int r0, int q, unsigned* ahi, unsigned* alo) {
    float2 x0 = *(const float2*)(g_h + (size_t)r0*16     + 2*q);
    float2 x1 = *(const float2*)(g_h + (size_t)(r0+8)*16 + 2*q);
    float2 x2 = *(const float2*)(g_h + (size_t)r0*16     + 2*q + 8);
    float2 x3 = *(const float2*)(g_h + (size_t)(r0+8)*16 + 2*q + 8);
    split2(x0, ahi[0], alo[0]);
    split2(x1, ahi[1], alo[1]);
    split2(x2, ahi[2], alo[2]);
    split2(x3, ahi[3], alo[3]);
}

// ---------------------------------------------------------------------------
// Prep: Wout[k][v] -> bf16 hi/lo B fragments in m16n8k16 col-major layout.
// B frag: b0 = (k=2q+{0,1}, col g), b1 = (k=2q+8+{0,1}, col g); lane = g*4+q.
// Storage: nt*128 + w*64 + lane*2 + j  (one LDG.64 per lane fetches b0,b1).
// ---------------------------------------------------------------------------
__global__ __launch_bounds__(256) void k_prep_w(const float* __restrict__ Wout) {
    int v = blockIdx.x*256 + threadIdx.x;   // 0..31999
    unsigned hi[16], lo[16];
    #pragma unroll
    for (int k = 0; k < 16; k++) {
        float w = Wout[(size_t)k*VOCAB + v];
        __nv_bfloat16 bh = __float2bfloat16(w);
        __nv_bfloat16 bl = __float2bfloat16(w - __bfloat162float(bh));
        hi[k] = (unsigned)__bfloat16_as_ushort(bh);
        lo[k] = (unsigned)__bfloat16_as_ushort(bl);
    }
    unsigned* base = g_Bw + (size_t)(v >> 3)*128;
    int lane4 = (v & 7)*4;                  // g*4, q added below
    #pragma unroll
    for (int q = 0; q < 4; q++) {
        #pragma unroll
        for (int j = 0; j < 2; j++) {
            int k = 2*q + 8*j;
            base[      (lane4 + q)*2 + j] = hi[k] | (hi[k+1] << 16);
            base[ 64 + (lane4 + q)*2 + j] = lo[k] | (lo[k+1] << 16);
        }
    }
}

// ---------------------------------------------------------------------------
// k_pre / k_gru — unchanged measured components (25us together)
// ---------------------------------------------------------------------------
__global__ __launch_bounds__(64) void k_pre(
    const int*   __restrict__ x,   const float* __restrict__ emb,
    const float* __restrict__ Wz1, const float* __restrict__ bz1,
    const float* __restrict__ Wr1, const float* __restrict__ br1,
    const float* __restrict__ Wh1, const float* __restrict__ bh1,
    const float* __restrict__ Wz2, const float* __restrict__ bz2,
    const float* __restrict__ Wr2, const float* __restrict__ br2,
    const float* __restrict__ Wh2, const float* __restrict__ bh2)
{
    int t = blockIdx.x, dir = blockIdx.y, b = threadIdx.x;
    int gid = (dir*SEQ + t)*BATCH + b;
    if (gid < NROWS) g_sum[gid] = 0.f;

    const float* Wz = dir ? Wz2 : Wz1;
    const float* Wr = dir ? Wr2 : Wr1;
    const float* Wh = dir ? Wh2 : Wh1;
    float az = (dir ? bz2 : bz1)[0];
    float ar = (dir ? br2 : br1)[0];
    const float* bh = dir ? bh2 : bh1;
    float ah[8];
    #pragma unroll
    for (int j = 0; j < 8; j++) ah[j] = bh[j];

    int idx = x[t*BATCH + b];
    const float* e = emb + (size_t)idx * EMB;
    float ev[32];
    #pragma unroll
    for (int k = 0; k < 8; k++) {
        float4 v4 = ((const float4*)e)[k];
        ev[4*k+0] = v4.x; ev[4*k+1] = v4.y; ev[4*k+2] = v4.z; ev[4*k+3] = v4.w;
    }
    #pragma unroll
    for (int k = 0; k < 32; k++) {
        float evk = ev[k];
        az += evk * Wz[8 + k];
        ar += evk * Wr[8 + k];
        #pragma unroll
        for (int j = 0; j < 8; j++) ah[j] += evk * Wh[(8 + k)*8 + j];
    }
    float* Ab = g_A + (size_t)((dir*SEQ + t)*10)*BATCH + b;
    Ab[0] = az;
    Ab[BATCH] = ar;
    #pragma unroll
    for (int j = 0; j < 8; j++) Ab[(2 + j)*BATCH] = ah[j];
}

__global__ __launch_bounds__(128) void k_gru(
    const float* __restrict__ Wz1, const float* __restrict__ Wr1, const float* __restrict__ Wh1,
    const float* __restrict__ Wz2, const float* __restrict__ Wr2, const float* __restrict__ Wh2)
{
    int tid = threadIdx.x;
    int dir = tid >> 6, b = tid & 63;
    const float* Wz = dir ? Wz2 : Wz1;
    const float* Wr = dir ? Wr2 : Wr1;
    const float* Wh = dir ? Wh2 : Wh1;

    float wz[8], wr[8], wh[64];
    #pragma unroll
    for (int i = 0; i < 8; i++) { wz[i] = Wz[i]; wr[i] = Wr[i]; }
    #pragma unroll
    for (int i = 0; i < 64; i++) wh[i] = Wh[i];

    float h[8];
    #pragma unroll
    for (int j = 0; j < 8; j++) h[j] = 0.f;

    for (int step = 0; step < SEQ; ++step) {
        int time = dir ? (SEQ - 1 - step) : step;

        float* gh = g_h + (size_t)(time*BATCH + b)*16 + dir*8;
        ((float4*)gh)[0] = make_float4(h[0], h[1], h[2], h[3]);
        ((float4*)gh)[1] = make_float4(h[4], h[5], h[6], h[7]);

        const float* A = g_A + (size_t)((dir*SEQ + time)*10)*BATCH + b;
        float zi = A[0], ri = A[BATCH];
        #pragma unroll
        for (int i = 0; i < 8; i++) { zi += h[i]*wz[i]; ri += h[i]*wr[i]; }
        float z = 1.f / (1.f + __expf(-zi));
        float r = 1.f / (1.f + __expf(-ri));
        float hc[8];
        #pragma unroll
        for (int j = 0; j < 8; j++) {
            float s = A[(2 + j)*BATCH];
            #pragma unroll
            for (int i = 0; i < 8; i++) s += (r*h[i]) * wh[i*8 + j];
            hc[j] = tanh_fast(s);
        }
        #pragma unroll
        for (int j = 0; j < 8; j++) h[j] += z * (hc[j] - h[j]);
    }
}

// ---------------------------------------------------------------------------
// MMA passes. Block = 256 thr = 8 warps (4 M-warps x 2 N-warps).
// Block tile: 64 rows x 256 vocab. Warp tile: 16 rows x 128 vocab (16 n8 tiles).
// Per tile: 3 mma (hi*Whi, lo*Whi, hi*Wlo), then immediate epilogue.
// ---------------------------------------------------------------------------
__global__ __launch_bounds__(256) void k_mma_sum(const float* __restrict__ bout)
{
    __shared__ float sb[256];
    int tid = threadIdx.x, lane = tid & 31, warp = tid >> 5;
    int mw = warp & 3, nw = warp >> 2;
    int n0 = blockIdx.x*256;
    sb[tid] = bout[n0 + tid];
    __syncthreads();

    int q = lane & 3, g = lane >> 2;
    int r0 = blockIdx.y*64 + mw*16 + g;
    unsigned ahi[4], alo[4];
    build_a(r0, q, ahi, alo);

    const unsigned* Bp = g_Bw + ((size_t)(n0 >> 3) + nw*16)*128;
    const float* sbw = sb + nw*128;
    float accA = 0.f, accB = 0.f;

    #pragma unroll
    for (int t = 0; t < 16; t++) {
        u64 bhw = *(const u64*)(Bp + t*128 +      lane*2);
        u64 blw = *(const u64*)(Bp + t*128 + 64 + lane*2);
        unsigned bh0 = (unsigned)bhw, bh1 = (unsigned)(bhw >> 32);
        unsigned bl0 = (unsigned)blw, bl1 = (unsigned)(blw >> 32);
        float c0 = 0.f, c1 = 0.f, c2 = 0.f, c3 = 0.f;
        mma_bf16(c0,c1,c2,c3, ahi[0],ahi[1],ahi[2],ahi[3], bh0,bh1);
        mma_bf16(c0,c1,c2,c3, alo[0],alo[1],alo[2],alo[3], bh0,bh1);
        mma_bf16(c0,c1,c2,c3, ahi[0],ahi[1],ahi[2],ahi[3], bl0,bl1);
        float b0 = sbw[t*8 + 2*q], b1 = sbw[t*8 + 2*q + 1];
        accA += __expf(c0 + b0) + __expf(c1 + b1);
        accB += __expf(c2 + b0) + __expf(c3 + b1);
    }
    accA += __shfl_xor_sync(0xffffffffu, accA, 1);
    accA += __shfl_xor_sync(0xffffffffu, accA, 2);
    accB += __shfl_xor_sync(0xffffffffu, accB, 1);
    accB += __shfl_xor_sync(0xffffffffu, accB, 2);
    if (q == 0) {
        atomicAdd(&g_sum[r0],     accA);
        atomicAdd(&g_sum[r0 + 8], accB);
    }
}

__global__ __launch_bounds__(256) void k_mma_write(
    const float* __restrict__ bout, float* __restrict__ out)
{
    __shared__ float sb[256];
    __shared__ float snls[64];
    int tid = threadIdx.x, lane = tid & 31, warp = tid >> 5;
    int mw = warp & 3, nw = warp >> 2;
    int n0 = blockIdx.x*256;
    sb[tid] = bout[n0 + tid];
    if (tid < 64) snls[tid] = -__logf(g_sum[blockIdx.y*64 + tid]);
    __syncthreads();

    int q = lane & 3, g = lane >> 2;
    int r0 = blockIdx.y*64 + mw*16 + g;
    unsigned ahi[4], alo[4];
    build_a(r0, q, ahi, alo);
    float nlsA = snls[mw*16 + g], nlsB = snls[mw*16 + g + 8];

    const unsigned* Bp = g_Bw + ((size_t)(n0 >> 3) + nw*16)*128;
    const float* sbw = sb + nw*128;
    float* rowA = out + (size_t)r0*VOCAB;
    float* rowB = out + (size_t)(r0 + 8)*VOCAB;
    int cb = n0 + nw*128 + 2*q;

    #pragma unroll
    for (int t = 0; t < 16; t++) {
        u64 bhw = *(const u64*)(Bp + t*128 +      lane*2);
        u64 blw = *(const u64*)(Bp + t*128 + 64 + lane*2);
        unsigned bh0 = (unsigned)bhw, bh1 = (unsigned)(bhw >> 32);
        unsigned bl0 = (unsigned)blw, bl1 = (unsigned)(blw >> 32);
        float c0 = 0.f, c1 = 0.f, c2 = 0.f, c3 = 0.f;
        mma_bf16(c0,c1,c2,c3, ahi[0],ahi[1],ahi[2],ahi[3], bh0,bh1);
        mma_bf16(c0,c1,c2,c3, alo[0],alo[1],alo[2],alo[3], bh0,bh1);
        mma_bf16(c0,c1,c2,c3, ahi[0],ahi[1],ahi[2],ahi[3], bl0,bl1);
        float b0 = sbw[t*8 + 2*q], b1 = sbw[t*8 + 2*q + 1];
        int col = cb + t*8;
        float o0 = c0 + b0 + nlsA, o1 = c1 + b1 + nlsA;
        float o2 = c2 + b0 + nlsB, o3 = c3 + b1 + nlsB;
        asm volatile("st.global.cs.v2.f32 [%0], {%1, %2};"
                     :: "l"(rowA + col), "f"(o0), "f"(o1) : "memory");
        asm volatile("st.global.cs.v2.f32 [%0], {%1, %2};"
                     :: "l"(rowB + col), "f"(o2), "f"(o3) : "memory");
    }
}

// ---------------------------------------------------------------------------
extern "C" void kernel_launch(void* const* d_in, const int* in_sizes, int n_in,
                              void* d_out, int out_size)
{
    const int*   x    = (const int*)  d_in[0];
    const float* emb  = (const float*)d_in[1];
    const float* Wz1  = (const float*)d_in[2];  const float* bz1 = (const float*)d_in[3];
    const float* Wr1  = (const float*)d_in[4];  const float* br1 = (const float*)d_in[5];
    const float* Wh1  = (const float*)d_in[6];  const float* bh1 = (const float*)d_in[7];
    const float* Wz2  = (const float*)d_in[8];  const float* bz2 = (const float*)d_in[9];
    const float* Wr2  = (const float*)d_in[10]; const float* br2 = (const float*)d_in[11];
    const float* Wh2  = (const float*)d_in[12]; const float* bh2 = (const float*)d_in[13];
    const float* Wout = (const float*)d_in[14]; const float* bout= (const float*)d_in[15];
    float* out = (float*)d_out;

    k_prep_w<<<VOCAB/256, 256>>>(Wout);
    k_pre<<<dim3(SEQ, 2), BATCH>>>(x, emb, Wz1, bz1, Wr1, br1, Wh1, bh1,
                                   Wz2, bz2, Wr2, br2, Wh2, bh2);
    k_gru<<<1, 128>>>(Wz1, Wr1, Wh1, Wz2, Wr2, Wh2);
    k_mma_sum  <<<dim3(VOCAB/256, NROWS/64), 256>>>(bout);
    k_mma_write<<<dim3(VOCAB/256, NROWS/64), 256>>>(bout, out);
}

// round 11
// speedup vs baseline: 2.0895x; 1.0308x over previous
#include <cuda_runtime.h>
#include <cuda_bf16.h>
#include <math.h>

#define VOCAB 32000
#define EMB   32
#define HID   8
#define SEQ   64
#define BATCH 64
#define NROWS (SEQ*BATCH)   /* 4096 */
#define NTILES (VOCAB/8)    /* 4000 n8 tiles */
#define LOG2E 1.4426950408889634f

typedef unsigned long long u64;

__device__ float g_A[2*SEQ*BATCH*10];
__device__ float g_h[NROWS*16];
__device__ float g_sum[NROWS];
// B fragments, per n8-tile, per lane: 4 contiguous u32 {hi_j0, hi_j1, lo_j0, lo_j1}
__device__ unsigned g_Bw[NTILES*128];    // 2 MB, unscaled (write pass)
__device__ unsigned g_Bs[NTILES*128];    // 2 MB, x log2e  (sum pass)

__device__ __forceinline__ float tanh_fast(float x) {
    float y; asm("tanh.approx.f32 %0, %1;" : "=f"(y) : "f"(x)); return y;
}
__device__ __forceinline__ float ex2_fast(float x) {
    float y; asm("ex2.approx.f32 %0, %1;" : "=f"(y) : "f"(x)); return y;
}

__device__ __forceinline__ void split2(float2 v, unsigned& hi, unsigned& lo) {
    __nv_bfloat16 hx = __float2bfloat16(v.x);
    __nv_bfloat16 hy = __float2bfloat16(v.y);
    __nv_bfloat16 lx = __float2bfloat16(v.x - __bfloat162float(hx));
    __nv_bfloat16 ly = __float2bfloat16(v.y - __bfloat162float(hy));
    hi = (unsigned)__bfloat16_as_ushort(hx) | ((unsigned)__bfloat16_as_ushort(hy) << 16);
    lo = (unsigned)__bfloat16_as_ushort(lx) | ((unsigned)__bfloat16_as_ushort(ly) << 16);
}

__device__ __forceinline__ void mma_bf16(
    float& c0, float& c1, float& c2, float& c3,
    unsigned a0, unsigned a1, unsigned a2, unsigned a3,
    unsigned b0, unsigned b1)
{
    asm volatile(
        "mma.sync.aligned.m16n8k16.row.col.f32.bf16.bf16.f32 "
        "{%0,%1,%2,%3}, {%4,%5,%6,%7}, {%8,%9}, {%0,%1,%2,%3};"
        : "+f"(c0), "+f"(c1), "+f"(c2), "+f"(c3)
        : "r"(a0), "r"(a1), "r"(a2), "r"(a3), "r"(b0), "r"(b1));
}

// A fragments (hi, lo) for rows r0, r0+8; q = lane%4.
__device__ __forceinline__ void build_a(int r0, int q, unsigned* ahi, unsigned* alo) {
    float2 x0 = *(const float2*)(g_h + (size_t)r0*16     + 2*q);
    float2 x1 = *(const float2*)(g_h + (size_t)(r0+8)*16 + 2*q);
    float2 x2 = *(const float2*)(g_h + (size_t)r0*16     + 2*q + 8);
    float2 x3 = *(const float2*)(g_h + (size_t)(r0+8)*16 + 2*q + 8);
    split2(x0, ahi[0], alo[0]);
    split2(x1, ahi[1], alo[1]);
    split2(x2, ahi[2], alo[2]);
    split2(x3, ahi[3], alo[3]);
}

// ---------------------------------------------------------------------------
// Merged prep: blocks [0,125) build B fragment images (unscaled + log2e-scaled);
// blocks [125,157) run the embedding/input-projection precompute (4 (t,dir)
// pairs per 256-thread block).
// ---------------------------------------------------------------------------
__global__ __launch_bounds__(256) void k_prep(
    const float* __restrict__ Wout,
    const int*   __restrict__ x,   const float* __restrict__ emb,
    const float* __restrict__ Wz1, const float* __restrict__ bz1,
    const float* __restrict__ Wr1, const float* __restrict__ br1,
    const float* __restrict__ Wh1, const float* __restrict__ bh1,
    const float* __restrict__ Wz2, const float* __restrict__ bz2,
    const float* __restrict__ Wr2, const float* __restrict__ br2,
    const float* __restrict__ Wh2, const float* __restrict__ bh2)
{
    int bx = blockIdx.x, tid = threadIdx.x;
    if (bx < 125) {
        int v = bx*256 + tid;   // 0..31999
        unsigned hiw[16], low[16], his[16], los[16];
        #pragma unroll
        for (int q = 0; q < 4; q++) {
            #pragma unroll
            for (int j = 0; j < 2; j++) {
                int k = 2*q + 8*j;
                float w0 = Wout[(size_t)k*VOCAB + v];
                float w1 = Wout[(size_t)(k+1)*VOCAB + v];
                unsigned h, l;
                split2(make_float2(w0, w1), h, l);
                hiw[q*2+j] = h; low[q*2+j] = l;
                split2(make_float2(w0*LOG2E, w1*LOG2E), h, l);
                his[q*2+j] = h; los[q*2+j] = l;
            }
        }
        int l = (v & 7)*4;               // g*4 (q varies below)
        unsigned* bw = g_Bw + (size_t)(v >> 3)*128;
        unsigned* bs = g_Bs + (size_t)(v >> 3)*128;
        #pragma unroll
        for (int q = 0; q < 4; q++) {
            bw[(l+q)*4 + 0] = hiw[q*2+0];
            bw[(l+q)*4 + 1] = hiw[q*2+1];
            bw[(l+q)*4 + 2] = low[q*2+0];
            bw[(l+q)*4 + 3] = low[q*2+1];
            bs[(l+q)*4 + 0] = his[q*2+0];
            bs[(l+q)*4 + 1] = his[q*2+1];
            bs[(l+q)*4 + 2] = los[q*2+0];
            bs[(l+q)*4 + 3] = los[q*2+1];
        }
        return;
    }
    // ---- pre path ----
    int pair = (bx - 125)*4 + (tid >> 6);   // 0..127
    int dir = pair >> 6, t = pair & 63, b = tid & 63;
    int gid = (dir*SEQ + t)*BATCH + b;
    if (gid < NROWS) g_sum[gid] = 0.f;

    const float* Wz = dir ? Wz2 : Wz1;
    const float* Wr = dir ? Wr2 : Wr1;
    const float* Wh = dir ? Wh2 : Wh1;
    float az = (dir ? bz2 : bz1)[0];
    float ar = (dir ? br2 : br1)[0];
    const float* bh = dir ? bh2 : bh1;
    float ah[8];
    #pragma unroll
    for (int j = 0; j < 8; j++) ah[j] = bh[j];

    int idx = x[t*BATCH + b];
    const float* e = emb + (size_t)idx * EMB;
    float ev[32];
    #pragma unroll
    for (int k = 0; k < 8; k++) {
        float4 v4 = ((const float4*)e)[k];
        ev[4*k+0] = v4.x; ev[4*k+1] = v4.y; ev[4*k+2] = v4.z; ev[4*k+3] = v4.w;
    }
    #pragma unroll
    for (int k = 0; k < 32; k++) {
        float evk = ev[k];
        az += evk * Wz[8 + k];
        ar += evk * Wr[8 + k];
        #pragma unroll
        for (int j = 0; j < 8; j++) ah[j] += evk * Wh[(8 + k)*8 + j];
    }
    float* Ab = g_A + (size_t)((dir*SEQ + t)*10)*BATCH + b;
    Ab[0] = az;
    Ab[BATCH] = ar;
    #pragma unroll
    for (int j = 0; j < 8; j++) Ab[(2 + j)*BATCH] = ah[j];
}

// ---------------------------------------------------------------------------
// Serial GRU — unchanged measured component.
// ---------------------------------------------------------------------------
__global__ __launch_bounds__(128) void k_gru(
    const float* __restrict__ Wz1, const float* __restrict__ Wr1, const float* __restrict__ Wh1,
    const float* __restrict__ Wz2, const float* __restrict__ Wr2, const float* __restrict__ Wh2)
{
    int tid = threadIdx.x;
    int dir = tid >> 6, b = tid & 63;
    const float* Wz = dir ? Wz2 : Wz1;
    const float* Wr = dir ? Wr2 : Wr1;
    const float* Wh = dir ? Wh2 : Wh1;

    float wz[8], wr[8], wh[64];
    #pragma unroll
    for (int i = 0; i < 8; i++) { wz[i] = Wz[i]; wr[i] = Wr[i]; }
    #pragma unroll
    for (int i = 0; i < 64; i++) wh[i] = Wh[i];

    float h[8];
    #pragma unroll
    for (int j = 0; j < 8; j++) h[j] = 0.f;

    for (int step = 0; step < SEQ; ++step) {
        int time = dir ? (SEQ - 1 - step) : step;

        float* gh = g_h + (size_t)(time*BATCH + b)*16 + dir*8;
        ((float4*)gh)[0] = make_float4(h[0], h[1], h[2], h[3]);
        ((float4*)gh)[1] = make_float4(h[4], h[5], h[6], h[7]);

        const float* A = g_A + (size_t)((dir*SEQ + time)*10)*BATCH + b;
        float zi = A[0], ri = A[BATCH];
        #pragma unroll
        for (int i = 0; i < 8; i++) { zi += h[i]*wz[i]; ri += h[i]*wr[i]; }
        float z = 1.f / (1.f + __expf(-zi));
        float r = 1.f / (1.f + __expf(-ri));
        float hc[8];
        #pragma unroll
        for (int j = 0; j < 8; j++) {
            float s = A[(2 + j)*BATCH];
            #pragma unroll
            for (int i = 0; i < 8; i++) s += (r*h[i]) * wh[i*8 + j];
            hc[j] = tanh_fast(s);
        }
        #pragma unroll
        for (int j = 0; j < 8; j++) h[j] += z * (hc[j] - h[j]);
    }
}

// ---------------------------------------------------------------------------
// MMA passes. Block 256 = 8 warps (4 M x 2 N). Block tile 64 rows x 256 vocab;
// warp tile 16 rows x 128 vocab (16 n8 tiles). Per tile: 1 LDG.128 (B hi+lo),
// bias preloaded as accumulator init, 3 mma, immediate epilogue.
// ---------------------------------------------------------------------------
__global__ __launch_bounds__(256) void k_mma_sum(const float* __restrict__ bout)
{
    __shared__ float sb[256];
    int tid = threadIdx.x, lane = tid & 31, warp = tid >> 5;
    int mw = warp & 3, nw = warp >> 2;
    int n0 = blockIdx.x*256;
    sb[tid] = bout[n0 + tid] * LOG2E;      // pre-scaled bias
    __syncthreads();

    int q = lane & 3, g = lane >> 2;
    int r0 = blockIdx.y*64 + mw*16 + g;
    unsigned ahi[4], alo[4];
    build_a(r0, q, ahi, alo);

    const unsigned* Bp = g_Bs + ((size_t)(n0 >> 3) + nw*16)*128;
    const float* sbw = sb + nw*128;
    float accA = 0.f, accB = 0.f;

    #pragma unroll
    for (int t = 0; t < 16; t++) {
        uint4 B = *(const uint4*)(Bp + t*128 + lane*4);
        float b0 = sbw[t*8 + 2*q], b1 = sbw[t*8 + 2*q + 1];
        float c0 = b0, c1 = b1, c2 = b0, c3 = b1;
        mma_bf16(c0,c1,c2,c3, ahi[0],ahi[1],ahi[2],ahi[3], B.x,B.y);
        mma_bf16(c0,c1,c2,c3, alo[0],alo[1],alo[2],alo[3], B.x,B.y);
        mma_bf16(c0,c1,c2,c3, ahi[0],ahi[1],ahi[2],ahi[3], B.z,B.w);
        accA += ex2_fast(c0) + ex2_fast(c1);
        accB += ex2_fast(c2) + ex2_fast(c3);
    }
    accA += __shfl_xor_sync(0xffffffffu, accA, 1);
    accA += __shfl_xor_sync(0xffffffffu, accA, 2);
    accB += __shfl_xor_sync(0xffffffffu, accB, 1);
    accB += __shfl_xor_sync(0xffffffffu, accB, 2);
    if (q == 0) {
        atomicAdd(&g_sum[r0],     accA);
        atomicAdd(&g_sum[r0 + 8], accB);
    }
}

__global__ __launch_bounds__(256) void k_mma_write(
    const float* __restrict__ bout, float* __restrict__ out)
{
    __shared__ float sb[256];
    __shared__ float snls[64];
    int tid = threadIdx.x, lane = tid & 31, warp = tid >> 5;
    int mw = warp & 3, nw = warp >> 2;
    int n0 = blockIdx.x*256;
    sb[tid] = bout[n0 + tid];
    if (tid < 64) snls[tid] = -__logf(g_sum[blockIdx.y*64 + tid]);
    __syncthreads();

    int q = lane & 3, g = lane >> 2;
    int r0 = blockIdx.y*64 + mw*16 + g;
    unsigned ahi[4], alo[4];
    build_a(r0, q, ahi, alo);
    float nlsA = snls[mw*16 + g], nlsB = snls[mw*16 + g + 8];

    const unsigned* Bp = g_Bw + ((size_t)(n0 >> 3) + nw*16)*128;
    const float* sbw = sb + nw*128;
    float* rowA = out + (size_t)r0*VOCAB;
    float* rowB = out + (size_t)(r0 + 8)*VOCAB;
    int cb = n0 + nw*128 + 2*q;

    #pragma unroll
    for (int t = 0; t < 16; t++) {
        uint4 B = *(const uint4*)(Bp + t*128 + lane*4);
        float b0 = sbw[t*8 + 2*q], b1 = sbw[t*8 + 2*q + 1];
        float c0 = b0, c1 = b1, c2 = b0, c3 = b1;
        mma_bf16(c0,c1,c2,c3, ahi[0],ahi[1],ahi[2],ahi[3], B.x,B.y);
        mma_bf16(c0,c1,c2,c3, alo[0],alo[1],alo[2],alo[3], B.x,B.y);
        mma_bf16(c0,c1,c2,c3, ahi[0],ahi[1],ahi[2],ahi[3], B.z,B.w);
        int col = cb + t*8;
        float o0 = c0 + nlsA, o1 = c1 + nlsA;
        float o2 = c2 + nlsB, o3 = c3 + nlsB;
        asm volatile("st.global.cs.v2.f32 [%0], {%1, %2};"
                     :: "l"(rowA + col), "f"(o0), "f"(o1) : "memory");
        asm volatile("st.global.cs.v2.f32 [%0], {%1, %2};"
                     :: "l"(rowB + col), "f"(o2), "f"(o3) : "memory");
    }
}

// ---------------------------------------------------------------------------
extern "C" void kernel_launch(void* const* d_in, const int* in_sizes, int n_in,
                              void* d_out, int out_size)
{
    const int*   x    = (const int*)  d_in[0];
    const float* emb  = (const float*)d_in[1];
    const float* Wz1  = (const float*)d_in[2];  const float* bz1 = (const float*)d_in[3];
    const float* Wr1  = (const float*)d_in[4];  const float* br1 = (const float*)d_in[5];
    const float* Wh1  = (const float*)d_in[6];  const float* bh1 = (const float*)d_in[7];
    const float* Wz2  = (const float*)d_in[8];  const float* bz2 = (const float*)d_in[9];
    const float* Wr2  = (const float*)d_in[10]; const float* br2 = (const float*)d_in[11];
    const float* Wh2  = (const float*)d_in[12]; const float* bh2 = (const float*)d_in[13];
    const float* Wout = (const float*)d_in[14]; const float* bout= (const float*)d_in[15];
    float* out = (float*)d_out;

    k_prep<<<125 + 32, 256>>>(Wout, x, emb, Wz1, bz1, Wr1, br1, Wh1, bh1,
                              Wz2, bz2, Wr2, br2, Wh2, bh2);
    k_gru<<<1, 128>>>(Wz1, Wr1, Wh1, Wz2, Wr2, Wh2);
    k_mma_sum  <<<dim3(VOCAB/256, NROWS/64), 256>>>(bout);
    k_mma_write<<<dim3(VOCAB/256, NROWS/64), 256>>>(bout, out);
}

// round 12
// speedup vs baseline: 2.3419x; 1.1208x over previous
#include <cuda_runtime.h>
#include <cuda_bf16.h>
#include <math.h>

#define VOCAB 32000
#define EMB   32
#define HID   8
#define SEQ   64
#define BATCH 64
#define NROWS (SEQ*BATCH)   /* 4096 */
#define NTILES (VOCAB/8)    /* 4000 n8 tiles */
#define LOG2E 1.4426950408889634f

typedef unsigned long long u64;

__device__ float g_A[2*SEQ*BATCH*10];
__device__ float g_h[NROWS*16];
__device__ float g_sum[NROWS];
// B fragments, per n8-tile, per lane: 4 contiguous u32 {hi_j0, hi_j1, lo_j0, lo_j1}
__device__ unsigned g_Bw[NTILES*128];    // 2 MB, unscaled (write pass)
__device__ unsigned g_Bs[NTILES*128];    // 2 MB, x log2e  (sum pass)

__device__ __forceinline__ float tanh_fast(float x) {
    float y; asm("tanh.approx.f32 %0, %1;" : "=f"(y) : "f"(x)); return y;
}
__device__ __forceinline__ float ex2_fast(float x) {
    float y; asm("ex2.approx.f32 %0, %1;" : "=f"(y) : "f"(x)); return y;
}

__device__ __forceinline__ void split2(float2 v, unsigned& hi, unsigned& lo) {
    __nv_bfloat16 hx = __float2bfloat16(v.x);
    __nv_bfloat16 hy = __float2bfloat16(v.y);
    __nv_bfloat16 lx = __float2bfloat16(v.x - __bfloat162float(hx));
    __nv_bfloat16 ly = __float2bfloat16(v.y - __bfloat162float(hy));
    hi = (unsigned)__bfloat16_as_ushort(hx) | ((unsigned)__bfloat16_as_ushort(hy) << 16);
    lo = (unsigned)__bfloat16_as_ushort(lx) | ((unsigned)__bfloat16_as_ushort(ly) << 16);
}

__device__ __forceinline__ void mma_bf16(
    float& c0, float& c1, float& c2, float& c3,
    unsigned a0, unsigned a1, unsigned a2, unsigned a3,
    unsigned b0, unsigned b1)
{
    asm volatile(
        "mma.sync.aligned.m16n8k16.row.col.f32.bf16.bf16.f32 "
        "{%0,%1,%2,%3}, {%4,%5,%6,%7}, {%8,%9}, {%0,%1,%2,%3};"
        : "+f"(c0), "+f"(c1), "+f"(c2), "+f"(c3)
        : "r"(a0), "r"(a1), "r"(a2), "r"(a3), "r"(b0), "r"(b1));
}

// A fragments (hi, lo) for rows r0, r0+8; q = lane%4.
__device__ __forceinline__ void build_a(int r0, int q, unsigned* ahi, unsigned* alo) {
    float2 x0 = *(const float2*)(g_h + (size_t)r0*16     + 2*q);
    float2 x1 = *(const float2*)(g_h + (size_t)(r0+8)*16 + 2*q);
    float2 x2 = *(const float2*)(g_h + (size_t)r0*16     + 2*q + 8);
    float2 x3 = *(const float2*)(g_h + (size_t)(r0+8)*16 + 2*q + 8);
    split2(x0, ahi[0], alo[0]);
    split2(x1, ahi[1], alo[1]);
    split2(x2, ahi[2], alo[2]);
    split2(x3, ahi[3], alo[3]);
}

// ---------------------------------------------------------------------------
// Merged prep: blocks [0,125) build B fragment images; blocks [125,157) run
// the embedding/input-projection precompute.
// ---------------------------------------------------------------------------
__global__ __launch_bounds__(256) void k_prep(
    const float* __restrict__ Wout,
    const int*   __restrict__ x,   const float* __restrict__ emb,
    const float* __restrict__ Wz1, const float* __restrict__ bz1,
    const float* __restrict__ Wr1, const float* __restrict__ br1,
    const float* __restrict__ Wh1, const float* __restrict__ bh1,
    const float* __restrict__ Wz2, const float* __restrict__ bz2,
    const float* __restrict__ Wr2, const float* __restrict__ br2,
    const float* __restrict__ Wh2, const float* __restrict__ bh2)
{
    int bx = blockIdx.x, tid = threadIdx.x;
    if (bx < 125) {
        int v = bx*256 + tid;   // 0..31999
        unsigned hiw[8], low[8], his[8], los[8];
        #pragma unroll
        for (int q = 0; q < 4; q++) {
            #pragma unroll
            for (int j = 0; j < 2; j++) {
                int k = 2*q + 8*j;
                float w0 = Wout[(size_t)k*VOCAB + v];
                float w1 = Wout[(size_t)(k+1)*VOCAB + v];
                unsigned h, l;
                split2(make_float2(w0, w1), h, l);
                hiw[q*2+j] = h; low[q*2+j] = l;
                split2(make_float2(w0*LOG2E, w1*LOG2E), h, l);
                his[q*2+j] = h; los[q*2+j] = l;
            }
        }
        int l = (v & 7)*4;
        unsigned* bw = g_Bw + (size_t)(v >> 3)*128;
        unsigned* bs = g_Bs + (size_t)(v >> 3)*128;
        #pragma unroll
        for (int q = 0; q < 4; q++) {
            bw[(l+q)*4 + 0] = hiw[q*2+0];
            bw[(l+q)*4 + 1] = hiw[q*2+1];
            bw[(l+q)*4 + 2] = low[q*2+0];
            bw[(l+q)*4 + 3] = low[q*2+1];
            bs[(l+q)*4 + 0] = his[q*2+0];
            bs[(l+q)*4 + 1] = his[q*2+1];
            bs[(l+q)*4 + 2] = los[q*2+0];
            bs[(l+q)*4 + 3] = los[q*2+1];
        }
        return;
    }
    // ---- pre path ----
    int pair = (bx - 125)*4 + (tid >> 6);   // 0..127
    int dir = pair >> 6, t = pair & 63, b = tid & 63;
    int gid = (dir*SEQ + t)*BATCH + b;
    if (gid < NROWS) g_sum[gid] = 0.f;

    const float* Wz = dir ? Wz2 : Wz1;
    const float* Wr = dir ? Wr2 : Wr1;
    const float* Wh = dir ? Wh2 : Wh1;
    float az = (dir ? bz2 : bz1)[0];
    float ar = (dir ? br2 : br1)[0];
    const float* bh = dir ? bh2 : bh1;
    float ah[8];
    #pragma unroll
    for (int j = 0; j < 8; j++) ah[j] = bh[j];

    int idx = x[t*BATCH + b];
    const float* e = emb + (size_t)idx * EMB;
    float ev[32];
    #pragma unroll
    for (int k = 0; k < 8; k++) {
        float4 v4 = ((const float4*)e)[k];
        ev[4*k+0] = v4.x; ev[4*k+1] = v4.y; ev[4*k+2] = v4.z; ev[4*k+3] = v4.w;
    }
    #pragma unroll
    for (int k = 0; k < 32; k++) {
        float evk = ev[k];
        az += evk * Wz[8 + k];
        ar += evk * Wr[8 + k];
        #pragma unroll
        for (int j = 0; j < 8; j++) ah[j] += evk * Wh[(8 + k)*8 + j];
    }
    float* Ab = g_A + (size_t)((dir*SEQ + t)*10)*BATCH + b;
    Ab[0] = az;
    Ab[BATCH] = ar;
    #pragma unroll
    for (int j = 0; j < 8; j++) Ab[(2 + j)*BATCH] = ah[j];
}

// ---------------------------------------------------------------------------
// Serial GRU — unchanged measured component.
// ---------------------------------------------------------------------------
__global__ __launch_bounds__(128) void k_gru(
    const float* __restrict__ Wz1, const float* __restrict__ Wr1, const float* __restrict__ Wh1,
    const float* __restrict__ Wz2, const float* __restrict__ Wr2, const float* __restrict__ Wh2)
{
    int tid = threadIdx.x;
    int dir = tid >> 6, b = tid & 63;
    const float* Wz = dir ? Wz2 : Wz1;
    const float* Wr = dir ? Wr2 : Wr1;
    const float* Wh = dir ? Wh2 : Wh1;

    float wz[8], wr[8], wh[64];
    #pragma unroll
    for (int i = 0; i < 8; i++) { wz[i] = Wz[i]; wr[i] = Wr[i]; }
    #pragma unroll
    for (int i = 0; i < 64; i++) wh[i] = Wh[i];

    float h[8];
    #pragma unroll
    for (int j = 0; j < 8; j++) h[j] = 0.f;

    for (int step = 0; step < SEQ; ++step) {
        int time = dir ? (SEQ - 1 - step) : step;

        float* gh = g_h + (size_t)(time*BATCH + b)*16 + dir*8;
        ((float4*)gh)[0] = make_float4(h[0], h[1], h[2], h[3]);
        ((float4*)gh)[1] = make_float4(h[4], h[5], h[6], h[7]);

        const float* A = g_A + (size_t)((dir*SEQ + time)*10)*BATCH + b;
        float zi = A[0], ri = A[BATCH];
        #pragma unroll
        for (int i = 0; i < 8; i++) { zi += h[i]*wz[i]; ri += h[i]*wr[i]; }
        float z = 1.f / (1.f + __expf(-zi));
        float r = 1.f / (1.f + __expf(-ri));
        float hc[8];
        #pragma unroll
        for (int j = 0; j < 8; j++) {
            float s = A[(2 + j)*BATCH];
            #pragma unroll
            for (int i = 0; i < 8; i++) s += (r*h[i]) * wh[i*8 + j];
            hc[j] = tanh_fast(s);
        }
        #pragma unroll
        for (int j = 0; j < 8; j++) h[j] += z * (hc[j] - h[j]);
    }
}

// ---------------------------------------------------------------------------
// Sum pass — unchanged from round 11.
// ---------------------------------------------------------------------------
__global__ __launch_bounds__(256) void k_mma_sum(const float* __restrict__ bout)
{
    __shared__ __align__(16) float sb[256];
    int tid = threadIdx.x, lane = tid & 31, warp = tid >> 5;
    int mw = warp & 3, nw = warp >> 2;
    int n0 = blockIdx.x*256;
    sb[tid] = bout[n0 + tid] * LOG2E;
    __syncthreads();

    int q = lane & 3, g = lane >> 2;
    int r0 = blockIdx.y*64 + mw*16 + g;
    unsigned ahi[4], alo[4];
    build_a(r0, q, ahi, alo);

    const unsigned* Bp = g_Bs + ((size_t)(n0 >> 3) + nw*16)*128;
    const float* sbw = sb + nw*128;
    float accA = 0.f, accB = 0.f;

    #pragma unroll
    for (int t = 0; t < 16; t++) {
        uint4 B = *(const uint4*)(Bp + t*128 + lane*4);
        float2 bb = *(const float2*)(sbw + t*8 + 2*q);
        float c0 = bb.x, c1 = bb.y, c2 = bb.x, c3 = bb.y;
        mma_bf16(c0,c1,c2,c3, ahi[0],ahi[1],ahi[2],ahi[3], B.x,B.y);
        mma_bf16(c0,c1,c2,c3, alo[0],alo[1],alo[2],alo[3], B.x,B.y);
        mma_bf16(c0,c1,c2,c3, ahi[0],ahi[1],ahi[2],ahi[3], B.z,B.w);
        accA += ex2_fast(c0) + ex2_fast(c1);
        accB += ex2_fast(c2) + ex2_fast(c3);
    }
    accA += __shfl_xor_sync(0xffffffffu, accA, 1);
    accA += __shfl_xor_sync(0xffffffffu, accA, 2);
    accB += __shfl_xor_sync(0xffffffffu, accB, 1);
    accB += __shfl_xor_sync(0xffffffffu, accB, 2);
    if (q == 0) {
        atomicAdd(&g_sum[r0],     accA);
        atomicAdd(&g_sum[r0 + 8], accB);
    }
}

// ---------------------------------------------------------------------------
// Write pass with transposed coalesced epilogue.
// Per warp: 16x32-col groups staged in XOR-swizzled smem (16B granules),
// then st.global.cs.v4 with 128B-per-row coalescing.
// ---------------------------------------------------------------------------
__global__ __launch_bounds__(256) void k_mma_write(
    const float* __restrict__ bout, float* __restrict__ out)
{
    __shared__ __align__(16) float sb[256];
    __shared__ float snls[64];
    __shared__ __align__(16) uint4 tsm[8][16*8];   // 16 KB: 8 warps x 16 rows x 8 granules

    int tid = threadIdx.x, lane = tid & 31, warp = tid >> 5;
    int mw = warp & 3, nw = warp >> 2;
    int n0 = blockIdx.x*256;
    sb[tid] = bout[n0 + tid];
    if (tid < 64) snls[tid] = -__logf(g_sum[blockIdx.y*64 + tid]);
    __syncthreads();

    int q = lane & 3, g = lane >> 2;
    int rowbase = blockIdx.y*64 + mw*16;
    int r0 = rowbase + g;
    unsigned ahi[4], alo[4];
    build_a(r0, q, ahi, alo);
    float nlsA = snls[mw*16 + g], nlsB = snls[mw*16 + g + 8];

    const unsigned* Bp = g_Bw + ((size_t)(n0 >> 3) + nw*16)*128;
    const float* sbw = sb + nw*128;
    float* tw = (float*)tsm[warp];
    int colbase = n0 + nw*128;
    int h = q & 1;                 // half of the 16B granule

    #pragma unroll
    for (int G = 0; G < 4; G++) {
        #pragma unroll
        for (int tt = 0; tt < 4; tt++) {
            int t = G*4 + tt;
            uint4 B = *(const uint4*)(Bp + t*128 + lane*4);
            float2 bb = *(const float2*)(sbw + t*8 + 2*q);
            float c0 = bb.x, c1 = bb.y, c2 = bb.x, c3 = bb.y;
            mma_bf16(c0,c1,c2,c3, ahi[0],ahi[1],ahi[2],ahi[3], B.x,B.y);
            mma_bf16(c0,c1,c2,c3, alo[0],alo[1],alo[2],alo[3], B.x,B.y);
            mma_bf16(c0,c1,c2,c3, ahi[0],ahi[1],ahi[2],ahi[3], B.z,B.w);
            int Gl = tt*2 + (q >> 1);              // logical 16B granule within 32-col group
            int pa = Gl ^ (g & 7);                  // physical granule (XOR swizzle)
            int pb = Gl ^ ((g + 8) & 7);
            *(float2*)(tw + (g*8 + pa)*4 + h*2)       = make_float2(c0 + nlsA, c1 + nlsA);
            *(float2*)(tw + ((g+8)*8 + pb)*4 + h*2)   = make_float2(c2 + nlsB, c3 + nlsB);
        }
        __syncwarp();
        #pragma unroll
        for (int i = 0; i < 4; i++) {
            int r = i*4 + (lane >> 3);
            int k = lane & 7;
            int p = k ^ (r & 7);
            uint4 vv = tsm[warp][r*8 + p];
            float* pd = out + (size_t)(rowbase + r)*VOCAB + colbase + G*32 + k*4;
            asm volatile("st.global.cs.v4.b32 [%0], {%1, %2, %3, %4};"
                         :: "l"(pd), "r"(vv.x), "r"(vv.y), "r"(vv.z), "r"(vv.w) : "memory");
        }
        __syncwarp();
    }
}

// ---------------------------------------------------------------------------
extern "C" void kernel_launch(void* const* d_in, const int* in_sizes, int n_in,
                              void* d_out, int out_size)
{
    const int*   x    = (const int*)  d_in[0];
    const float* emb  = (const float*)d_in[1];
    const float* Wz1  = (const float*)d_in[2];  const float* bz1 = (const float*)d_in[3];
    const float* Wr1  = (const float*)d_in[4];  const float* br1 = (const float*)d_in[5];
    const float* Wh1  = (const float*)d_in[6];  const float* bh1 = (const float*)d_in[7];
    const float* Wz2  = (const float*)d_in[8];  const float* bz2 = (const float*)d_in[9];
    const float* Wr2  = (const float*)d_in[10]; const float* br2 = (const float*)d_in[11];
    const float* Wh2  = (const float*)d_in[12]; const float* bh2 = (const float*)d_in[13];
    const float* Wout = (const float*)d_in[14]; const float* bout= (const float*)d_in[15];
    float* out = (float*)d_out;

    k_prep<<<125 + 32, 256>>>(Wout, x, emb, Wz1, bz1, Wr1, br1, Wh1, bh1,
                              Wz2, bz2, Wr2, br2, Wh2, bh2);
    k_gru<<<1, 128>>>(Wz1, Wr1, Wh1, Wz2, Wr2, Wh2);
    k_mma_sum  <<<dim3(VOCAB/256, NROWS/64), 256>>>(bout);
    k_mma_write<<<dim3(VOCAB/256, NROWS/64), 256>>>(bout, out);
}

// round 13
// speedup vs baseline: 2.4064x; 1.0276x over previous
#include <cuda_runtime.h>
#include <cuda_bf16.h>
#include <math.h>

#define VOCAB 32000
#define EMB   32
#define HID   8
#define SEQ   64
#define BATCH 64
#define NROWS (SEQ*BATCH)   /* 4096 */
#define NTILES (VOCAB/8)    /* 4000 n8 tiles */
#define NTP    (NTILES/2)   /* 2000 tile-pairs */
#define LOG2E 1.4426950408889634f

typedef unsigned long long u64;

__device__ float g_A[2*SEQ*BATCH*10];
__device__ float g_h[NROWS*16];
__device__ float g_sum[NROWS];
// B fragments (bf16 round-to-nearest), per tile-PAIR per lane: uint4
// {b0(t_even), b1(t_even), b0(t_odd), b1(t_odd)}
__device__ unsigned g_B[NTP*128];        // 1 MB

__device__ __forceinline__ float tanh_fast(float x) {
    float y; asm("tanh.approx.f32 %0, %1;" : "=f"(y) : "f"(x)); return y;
}
__device__ __forceinline__ float ex2_fast(float x) {
    float y; asm("ex2.approx.f32 %0, %1;" : "=f"(y) : "f"(x)); return y;
}

__device__ __forceinline__ unsigned pack_bf16(float x, float y) {
    return (unsigned)__bfloat16_as_ushort(__float2bfloat16(x))
         | ((unsigned)__bfloat16_as_ushort(__float2bfloat16(y)) << 16);
}
__device__ __forceinline__ void split2(float2 v, unsigned& hi, unsigned& lo) {
    __nv_bfloat16 hx = __float2bfloat16(v.x);
    __nv_bfloat16 hy = __float2bfloat16(v.y);
    __nv_bfloat16 lx = __float2bfloat16(v.x - __bfloat162float(hx));
    __nv_bfloat16 ly = __float2bfloat16(v.y - __bfloat162float(hy));
    hi = (unsigned)__bfloat16_as_ushort(hx) | ((unsigned)__bfloat16_as_ushort(hy) << 16);
    lo = (unsigned)__bfloat16_as_ushort(lx) | ((unsigned)__bfloat16_as_ushort(ly) << 16);
}

__device__ __forceinline__ void mma_bf16(
    float& c0, float& c1, float& c2, float& c3,
    unsigned a0, unsigned a1, unsigned a2, unsigned a3,
    unsigned b0, unsigned b1)
{
    asm volatile(
        "mma.sync.aligned.m16n8k16.row.col.f32.bf16.bf16.f32 "
        "{%0,%1,%2,%3}, {%4,%5,%6,%7}, {%8,%9}, {%0,%1,%2,%3};"
        : "+f"(c0), "+f"(c1), "+f"(c2), "+f"(c3)
        : "r"(a0), "r"(a1), "r"(a2), "r"(a3), "r"(b0), "r"(b1));
}

// A fragments (hi, lo) for rows r0, r0+8 (scaled); q = lane%4.
__device__ __forceinline__ void build_a(int r0, int q, float scale,
                                        unsigned* ahi, unsigned* alo) {
    float2 x0 = *(const float2*)(g_h + (size_t)r0*16     + 2*q);
    float2 x1 = *(const float2*)(g_h + (size_t)(r0+8)*16 + 2*q);
    float2 x2 = *(const float2*)(g_h + (size_t)r0*16     + 2*q + 8);
    float2 x3 = *(const float2*)(g_h + (size_t)(r0+8)*16 + 2*q + 8);
    x0.x *= scale; x0.y *= scale; x1.x *= scale; x1.y *= scale;
    x2.x *= scale; x2.y *= scale; x3.x *= scale; x3.y *= scale;
    split2(x0, ahi[0], alo[0]);
    split2(x1, ahi[1], alo[1]);
    split2(x2, ahi[2], alo[2]);
    split2(x3, ahi[3], alo[3]);
}

// ---------------------------------------------------------------------------
// Merged prep: blocks [0,125) build the B fragment image; blocks [125,157)
// run the embedding/input-projection precompute.
// ---------------------------------------------------------------------------
__global__ __launch_bounds__(256) void k_prep(
    const float* __restrict__ Wout,
    const int*   __restrict__ x,   const float* __restrict__ emb,
    const float* __restrict__ Wz1, const float* __restrict__ bz1,
    const float* __restrict__ Wr1, const float* __restrict__ br1,
    const float* __restrict__ Wh1, const float* __restrict__ bh1,
    const float* __restrict__ Wz2, const float* __restrict__ bz2,
    const float* __restrict__ Wr2, const float* __restrict__ br2,
    const float* __restrict__ Wh2, const float* __restrict__ bh2)
{
    int bx = blockIdx.x, tid = threadIdx.x;
    if (bx < 125) {
        int v = bx*256 + tid;   // 0..31999
        int g = v & 7, half = (v >> 3) & 1, tp = v >> 4;
        unsigned* bp = g_B + (size_t)tp*128 + half*2;
        #pragma unroll
        for (int q = 0; q < 4; q++) {
            float w0 = Wout[(size_t)(2*q)  *VOCAB + v];
            float w1 = Wout[(size_t)(2*q+1)*VOCAB + v];
            float w2 = Wout[(size_t)(2*q+8)*VOCAB + v];
            float w3 = Wout[(size_t)(2*q+9)*VOCAB + v];
            bp[(g*4+q)*4 + 0] = pack_bf16(w0, w1);
            bp[(g*4+q)*4 + 1] = pack_bf16(w2, w3);
        }
        return;
    }
    // ---- pre path ----
    int pair = (bx - 125)*4 + (tid >> 6);   // 0..127
    int dir = pair >> 6, t = pair & 63, b = tid & 63;
    int gid = (dir*SEQ + t)*BATCH + b;
    if (gid < NROWS) g_sum[gid] = 0.f;

    const float* Wz = dir ? Wz2 : Wz1;
    const float* Wr = dir ? Wr2 : Wr1;
    const float* Wh = dir ? Wh2 : Wh1;
    float az = (dir ? bz2 : bz1)[0];
    float ar = (dir ? br2 : br1)[0];
    const float* bh = dir ? bh2 : bh1;
    float ah[8];
    #pragma unroll
    for (int j = 0; j < 8; j++) ah[j] = bh[j];

    int idx = x[t*BATCH + b];
    const float* e = emb + (size_t)idx * EMB;
    float ev[32];
    #pragma unroll
    for (int k = 0; k < 8; k++) {
        float4 v4 = ((const float4*)e)[k];
        ev[4*k+0] = v4.x; ev[4*k+1] = v4.y; ev[4*k+2] = v4.z; ev[4*k+3] = v4.w;
    }
    #pragma unroll
    for (int k = 0; k < 32; k++) {
        float evk = ev[k];
        az += evk * Wz[8 + k];
        ar += evk * Wr[8 + k];
        #pragma unroll
        for (int j = 0; j < 8; j++) ah[j] += evk * Wh[(8 + k)*8 + j];
    }
    float* Ab = g_A + (size_t)((dir*SEQ + t)*10)*BATCH + b;
    Ab[0] = az;
    Ab[BATCH] = ar;
    #pragma unroll
    for (int j = 0; j < 8; j++) Ab[(2 + j)*BATCH] = ah[j];
}

// ---------------------------------------------------------------------------
// Serial GRU — unchanged measured component.
// ---------------------------------------------------------------------------
__global__ __launch_bounds__(128) void k_gru(
    const float* __restrict__ Wz1, const float* __restrict__ Wr1, const float* __restrict__ Wh1,
    const float* __restrict__ Wz2, const float* __restrict__ Wr2, const float* __restrict__ Wh2)
{
    int tid = threadIdx.x;
    int dir = tid >> 6, b = tid & 63;
    const float* Wz = dir ? Wz2 : Wz1;
    const float* Wr = dir ? Wr2 : Wr1;
    const float* Wh = dir ? Wh2 : Wh1;

    float wz[8], wr[8], wh[64];
    #pragma unroll
    for (int i = 0; i < 8; i++) { wz[i] = Wz[i]; wr[i] = Wr[i]; }
    #pragma unroll
    for (int i = 0; i < 64; i++) wh[i] = Wh[i];

    float h[8];
    #pragma unroll
    for (int j = 0; j < 8; j++) h[j] = 0.f;

    for (int step = 0; step < SEQ; ++step) {
        int time = dir ? (SEQ - 1 - step) : step;

        float* gh = g_h + (size_t)(time*BATCH + b)*16 + dir*8;
        ((float4*)gh)[0] = make_float4(h[0], h[1], h[2], h[3]);
        ((float4*)gh)[1] = make_float4(h[4], h[5], h[6], h[7]);

        const float* A = g_A + (size_t)((dir*SEQ + time)*10)*BATCH + b;
        float zi = A[0], ri = A[BATCH];
        #pragma unroll
        for (int i = 0; i < 8; i++) { zi += h[i]*wz[i]; ri += h[i]*wr[i]; }
        float z = 1.f / (1.f + __expf(-zi));
        float r = 1.f / (1.f + __expf(-ri));
        float hc[8];
        #pragma unroll
        for (int j = 0; j < 8; j++) {
            float s = A[(2 + j)*BATCH];
            #pragma unroll
            for (int i = 0; i < 8; i++) s += (r*h[i]) * wh[i*8 + j];
            hc[j] = tanh_fast(s);
        }
        #pragma unroll
        for (int j = 0; j < 8; j++) h[j] += z * (hc[j] - h[j]);
    }
}

// ---------------------------------------------------------------------------
// Sum pass: A pre-scaled by log2e (hi/lo split), B single bf16 -> 2 MMAs/tile.
// ---------------------------------------------------------------------------
__global__ __launch_bounds__(256) void k_mma_sum(const float* __restrict__ bout)
{
    __shared__ __align__(16) float sb[256];
    int tid = threadIdx.x, lane = tid & 31, warp = tid >> 5;
    int mw = warp & 3, nw = warp >> 2;
    int n0 = blockIdx.x*256;
    sb[tid] = bout[n0 + tid] * LOG2E;
    __syncthreads();

    int q = lane & 3, g = lane >> 2;
    int r0 = blockIdx.y*64 + mw*16 + g;
    unsigned ahi[4], alo[4];
    build_a(r0, q, LOG2E, ahi, alo);

    const unsigned* Bp = g_B + ((size_t)(n0 >> 4) + nw*8)*128;
    const float* sbw = sb + nw*128;
    float accA = 0.f, accB = 0.f;

    #pragma unroll
    for (int tp = 0; tp < 8; tp++) {
        uint4 B = *(const uint4*)(Bp + tp*128 + lane*4);
        float2 bb0 = *(const float2*)(sbw + tp*16 + 2*q);
        float c0 = bb0.x, c1 = bb0.y, c2 = bb0.x, c3 = bb0.y;
        mma_bf16(c0,c1,c2,c3, ahi[0],ahi[1],ahi[2],ahi[3], B.x,B.y);
        mma_bf16(c0,c1,c2,c3, alo[0],alo[1],alo[2],alo[3], B.x,B.y);
        accA += ex2_fast(c0) + ex2_fast(c1);
        accB += ex2_fast(c2) + ex2_fast(c3);
        float2 bb1 = *(const float2*)(sbw + tp*16 + 8 + 2*q);
        float d0 = bb1.x, d1 = bb1.y, d2 = bb1.x, d3 = bb1.y;
        mma_bf16(d0,d1,d2,d3, ahi[0],ahi[1],ahi[2],ahi[3], B.z,B.w);
        mma_bf16(d0,d1,d2,d3, alo[0],alo[1],alo[2],alo[3], B.z,B.w);
        accA += ex2_fast(d0) + ex2_fast(d1);
        accB += ex2_fast(d2) + ex2_fast(d3);
    }
    accA += __shfl_xor_sync(0xffffffffu, accA, 1);
    accA += __shfl_xor_sync(0xffffffffu, accA, 2);
    accB += __shfl_xor_sync(0xffffffffu, accB, 1);
    accB += __shfl_xor_sync(0xffffffffu, accB, 2);
    if (q == 0) {
        atomicAdd(&g_sum[r0],     accA);
        atomicAdd(&g_sum[r0 + 8], accB);
    }
}

// ---------------------------------------------------------------------------
// Write pass: 2 MMAs/tile + transposed coalesced epilogue (XOR-swizzled smem).
// ---------------------------------------------------------------------------
__global__ __launch_bounds__(256) void k_mma_write(
    const float* __restrict__ bout, float* __restrict__ out)
{
    __shared__ __align__(16) float sb[256];
    __shared__ float snls[64];
    __shared__ __align__(16) uint4 tsm[8][16*8];   // 16 KB

    int tid = threadIdx.x, lane = tid & 31, warp = tid >> 5;
    int mw = warp & 3, nw = warp >> 2;
    int n0 = blockIdx.x*256;
    sb[tid] = bout[n0 + tid];
    if (tid < 64) snls[tid] = -__logf(g_sum[blockIdx.y*64 + tid]);
    __syncthreads();

    int q = lane & 3, g = lane >> 2;
    int rowbase = blockIdx.y*64 + mw*16;
    int r0 = rowbase + g;
    unsigned ahi[4], alo[4];
    build_a(r0, q, 1.0f, ahi, alo);
    float nlsA = snls[mw*16 + g], nlsB = snls[mw*16 + g + 8];

    const unsigned* Bp = g_B + ((size_t)(n0 >> 4) + nw*8)*128;
    const float* sbw = sb + nw*128;
    float* tw = (float*)tsm[warp];
    int colbase = n0 + nw*128;
    int h = q & 1;

    #pragma unroll
    for (int G = 0; G < 4; G++) {
        #pragma unroll
        for (int tpp = 0; tpp < 2; tpp++) {
            int tp = G*2 + tpp;
            uint4 B = *(const uint4*)(Bp + tp*128 + lane*4);
            #pragma unroll
            for (int hf = 0; hf < 2; hf++) {
                int t = tp*2 + hf;
                int tt = tpp*2 + hf;
                unsigned b0 = hf ? B.z : B.x;
                unsigned b1 = hf ? B.w : B.y;
                float2 bb = *(const float2*)(sbw + t*8 + 2*q);
                float c0 = bb.x, c1 = bb.y, c2 = bb.x, c3 = bb.y;
                mma_bf16(c0,c1,c2,c3, ahi[0],ahi[1],ahi[2],ahi[3], b0,b1);
                mma_bf16(c0,c1,c2,c3, alo[0],alo[1],alo[2],alo[3], b0,b1);
                int Gl = tt*2 + (q >> 1);
                int pa = Gl ^ (g & 7);
                int pb = Gl ^ ((g + 8) & 7);
                *(float2*)(tw + (g*8 + pa)*4 + h*2)     = make_float2(c0 + nlsA, c1 + nlsA);
                *(float2*)(tw + ((g+8)*8 + pb)*4 + h*2) = make_float2(c2 + nlsB, c3 + nlsB);
            }
        }
        __syncwarp();
        #pragma unroll
        for (int i = 0; i < 4; i++) {
            int r = i*4 + (lane >> 3);
            int k = lane & 7;
            int p = k ^ (r & 7);
            uint4 vv = tsm[warp][r*8 + p];
            float* pd = out + (size_t)(rowbase + r)*VOCAB + colbase + G*32 + k*4;
            asm volatile("st.global.cs.v4.b32 [%0], {%1, %2, %3, %4};"
                         :: "l"(pd), "r"(vv.x), "r"(vv.y), "r"(vv.z), "r"(vv.w) : "memory");
        }
        __syncwarp();
    }
}

// ---------------------------------------------------------------------------
extern "C" void kernel_launch(void* const* d_in, const int* in_sizes, int n_in,
                              void* d_out, int out_size)
{
    const int*   x    = (const int*)  d_in[0];
    const float* emb  = (const float*)d_in[1];
    const float* Wz1  = (const float*)d_in[2];  const float* bz1 = (const float*)d_in[3];
    const float* Wr1  = (const float*)d_in[4];  const float* br1 = (const float*)d_in[5];
    const float* Wh1  = (const float*)d_in[6];  const float* bh1 = (const float*)d_in[7];
    const float* Wz2  = (const float*)d_in[8];  const float* bz2 = (const float*)d_in[9];
    const float* Wr2  = (const float*)d_in[10]; const float* br2 = (const float*)d_in[11];
    const float* Wh2  = (const float*)d_in[12]; const float* bh2 = (const float*)d_in[13];
    const float* Wout = (const float*)d_in[14]; const float* bout= (const float*)d_in[15];
    float* out = (float*)d_out;

    k_prep<<<125 + 32, 256>>>(Wout, x, emb, Wz1, bz1, Wr1, br1, Wh1, bh1,
                              Wz2, bz2, Wr2, br2, Wh2, bh2);
    k_gru<<<1, 128>>>(Wz1, Wr1, Wh1, Wz2, Wr2, Wh2);
    k_mma_sum  <<<dim3(VOCAB/256, NROWS/64), 256>>>(bout);
    k_mma_write<<<dim3(VOCAB/256, NROWS/64), 256>>>(bout, out);
}

// round 14
// speedup vs baseline: 2.4717x; 1.0271x over previous
#include <cuda_runtime.h>
#include <cuda_bf16.h>
#include <math.h>

#define VOCAB 32000
#define EMB   32
#define HID   8
#define SEQ   64
#define BATCH 64
#define NROWS (SEQ*BATCH)   /* 4096 */
#define NTILES (VOCAB/8)    /* 4000 n8 tiles */
#define NTP    (NTILES/2)   /* 2000 tile-pairs */
#define LOG2E 1.4426950408889634f

typedef unsigned long long u64;

__device__ float g_A[2*SEQ*BATCH*10];
__device__ float g_h[NROWS*16];
__device__ float g_sum[NROWS];
// B fragments (bf16), per tile-PAIR per lane: uint4 {b0_e, b1_e, b0_o, b1_o}
__device__ unsigned g_B[NTP*128];        // 1 MB

__device__ __forceinline__ float tanh_fast(float x) {
    float y; asm("tanh.approx.f32 %0, %1;" : "=f"(y) : "f"(x)); return y;
}
__device__ __forceinline__ float ex2_fast(float x) {
    float y; asm("ex2.approx.f32 %0, %1;" : "=f"(y) : "f"(x)); return y;
}
__device__ __forceinline__ unsigned pack_bf16(float x, float y) {
    return (unsigned)__bfloat16_as_ushort(__float2bfloat16(x))
         | ((unsigned)__bfloat16_as_ushort(__float2bfloat16(y)) << 16);
}
__device__ __forceinline__ void split2(float2 v, unsigned& hi, unsigned& lo) {
    __nv_bfloat16 hx = __float2bfloat16(v.x);
    __nv_bfloat16 hy = __float2bfloat16(v.y);
    __nv_bfloat16 lx = __float2bfloat16(v.x - __bfloat162float(hx));
    __nv_bfloat16 ly = __float2bfloat16(v.y - __bfloat162float(hy));
    hi = (unsigned)__bfloat16_as_ushort(hx) | ((unsigned)__bfloat16_as_ushort(hy) << 16);
    lo = (unsigned)__bfloat16_as_ushort(lx) | ((unsigned)__bfloat16_as_ushort(ly) << 16);
}

__device__ __forceinline__ void mma_bf16(
    float& c0, float& c1, float& c2, float& c3,
    unsigned a0, unsigned a1, unsigned a2, unsigned a3,
    unsigned b0, unsigned b1)
{
    asm volatile(
        "mma.sync.aligned.m16n8k16.row.col.f32.bf16.bf16.f32 "
        "{%0,%1,%2,%3}, {%4,%5,%6,%7}, {%8,%9}, {%0,%1,%2,%3};"
        : "+f"(c0), "+f"(c1), "+f"(c2), "+f"(c3)
        : "r"(a0), "r"(a1), "r"(a2), "r"(a3), "r"(b0), "r"(b1));
}

__device__ __forceinline__ void build_a(int r0, int q, float scale,
                                        unsigned* ahi, unsigned* alo) {
    float2 x0 = *(const float2*)(g_h + (size_t)r0*16     + 2*q);
    float2 x1 = *(const float2*)(g_h + (size_t)(r0+8)*16 + 2*q);
    float2 x2 = *(const float2*)(g_h + (size_t)r0*16     + 2*q + 8);
    float2 x3 = *(const float2*)(g_h + (size_t)(r0+8)*16 + 2*q + 8);
    x0.x *= scale; x0.y *= scale; x1.x *= scale; x1.y *= scale;
    x2.x *= scale; x2.y *= scale; x3.x *= scale; x3.y *= scale;
    split2(x0, ahi[0], alo[0]);
    split2(x1, ahi[1], alo[1]);
    split2(x2, ahi[2], alo[2]);
    split2(x3, ahi[3], alo[3]);
}

// ---------------------------------------------------------------------------
// Kernel 0: embedding gather + input-projection precompute (32 blocks x 256).
// ---------------------------------------------------------------------------
__global__ __launch_bounds__(256) void k_pre(
    const int*   __restrict__ x,   const float* __restrict__ emb,
    const float* __restrict__ Wz1, const float* __restrict__ bz1,
    const float* __restrict__ Wr1, const float* __restrict__ br1,
    const float* __restrict__ Wh1, const float* __restrict__ bh1,
    const float* __restrict__ Wz2, const float* __restrict__ bz2,
    const float* __restrict__ Wr2, const float* __restrict__ br2,
    const float* __restrict__ Wh2, const float* __restrict__ bh2)
{
    int tid = threadIdx.x;
    int pair = blockIdx.x*4 + (tid >> 6);   // 0..127
    int dir = pair >> 6, t = pair & 63, b = tid & 63;
    int gid = (dir*SEQ + t)*BATCH + b;
    if (gid < NROWS) g_sum[gid] = 0.f;

    const float* Wz = dir ? Wz2 : Wz1;
    const float* Wr = dir ? Wr2 : Wr1;
    const float* Wh = dir ? Wh2 : Wh1;
    float az = (dir ? bz2 : bz1)[0];
    float ar = (dir ? br2 : br1)[0];
    const float* bh = dir ? bh2 : bh1;
    float ah[8];
    #pragma unroll
    for (int j = 0; j < 8; j++) ah[j] = bh[j];

    int idx = x[t*BATCH + b];
    const float* e = emb + (size_t)idx * EMB;
    float ev[32];
    #pragma unroll
    for (int k = 0; k < 8; k++) {
        float4 v4 = ((const float4*)e)[k];
        ev[4*k+0] = v4.x; ev[4*k+1] = v4.y; ev[4*k+2] = v4.z; ev[4*k+3] = v4.w;
    }
    #pragma unroll
    for (int k = 0; k < 32; k++) {
        float evk = ev[k];
        az += evk * Wz[8 + k];
        ar += evk * Wr[8 + k];
        #pragma unroll
        for (int j = 0; j < 8; j++) ah[j] += evk * Wh[(8 + k)*8 + j];
    }
    float* Ab = g_A + (size_t)((dir*SEQ + t)*10)*BATCH + b;
    Ab[0] = az;
    Ab[BATCH] = ar;
    #pragma unroll
    for (int j = 0; j < 8; j++) Ab[(2 + j)*BATCH] = ah[j];
}

// ---------------------------------------------------------------------------
// Kernel 1: block 0 runs the serial GRU (128 threads); blocks 1..125 build
// the bf16 B-fragment image. Overlaps the serial recurrence with prep work.
// ---------------------------------------------------------------------------
__global__ __launch_bounds__(256) void k_gru_prep(
    const float* __restrict__ Wout,
    const float* __restrict__ Wz1, const float* __restrict__ Wr1, const float* __restrict__ Wh1,
    const float* __restrict__ Wz2, const float* __restrict__ Wr2, const float* __restrict__ Wh2)
{
    int bx = blockIdx.x, tid = threadIdx.x;
    if (bx > 0) {
        int v = (bx - 1)*256 + tid;   // 0..31999
        int g = v & 7, half = (v >> 3) & 1, tp = v >> 4;
        unsigned* bp = g_B + (size_t)tp*128 + half*2;
        #pragma unroll
        for (int q = 0; q < 4; q++) {
            float w0 = Wout[(size_t)(2*q)  *VOCAB + v];
            float w1 = Wout[(size_t)(2*q+1)*VOCAB + v];
            float w2 = Wout[(size_t)(2*q+8)*VOCAB + v];
            float w3 = Wout[(size_t)(2*q+9)*VOCAB + v];
            bp[(g*4+q)*4 + 0] = pack_bf16(w0, w1);
            bp[(g*4+q)*4 + 1] = pack_bf16(w2, w3);
        }
        return;
    }
    if (tid >= 128) return;
    // ---- serial GRU (2 dirs x 64 batches) ----
    int dir = tid >> 6, b = tid & 63;
    const float* Wz = dir ? Wz2 : Wz1;
    const float* Wr = dir ? Wr2 : Wr1;
    const float* Wh = dir ? Wh2 : Wh1;

    float wz[8], wr[8], wh[64];
    #pragma unroll
    for (int i = 0; i < 8; i++) { wz[i] = Wz[i]; wr[i] = Wr[i]; }
    #pragma unroll
    for (int i = 0; i < 64; i++) wh[i] = Wh[i];

    float h[8];
    #pragma unroll
    for (int j = 0; j < 8; j++) h[j] = 0.f;

    for (int step = 0; step < SEQ; ++step) {
        int time = dir ? (SEQ - 1 - step) : step;

        float* gh = g_h + (size_t)(time*BATCH + b)*16 + dir*8;
        ((float4*)gh)[0] = make_float4(h[0], h[1], h[2], h[3]);
        ((float4*)gh)[1] = make_float4(h[4], h[5], h[6], h[7]);

        const float* A = g_A + (size_t)((dir*SEQ + time)*10)*BATCH + b;
        float zi = A[0], ri = A[BATCH];
        #pragma unroll
        for (int i = 0; i < 8; i++) { zi += h[i]*wz[i]; ri += h[i]*wr[i]; }
        float z = 1.f / (1.f + __expf(-zi));
        float r = 1.f / (1.f + __expf(-ri));
        float hc[8];
        #pragma unroll
        for (int j = 0; j < 8; j++) {
            float s = A[(2 + j)*BATCH];
            #pragma unroll
            for (int i = 0; i < 8; i++) s += (r*h[i]) * wh[i*8 + j];
            hc[j] = tanh_fast(s);
        }
        #pragma unroll
        for (int j = 0; j < 8; j++) h[j] += z * (hc[j] - h[j]);
    }
}

// ---------------------------------------------------------------------------
// Sum pass — unchanged from round 13 (measured component).
// ---------------------------------------------------------------------------
__global__ __launch_bounds__(256) void k_mma_sum(const float* __restrict__ bout)
{
    __shared__ __align__(16) float sb[256];
    int tid = threadIdx.x, lane = tid & 31, warp = tid >> 5;
    int mw = warp & 3, nw = warp >> 2;
    int n0 = blockIdx.x*256;
    sb[tid] = bout[n0 + tid] * LOG2E;
    __syncthreads();

    int q = lane & 3, g = lane >> 2;
    int r0 = blockIdx.y*64 + mw*16 + g;
    unsigned ahi[4], alo[4];
    build_a(r0, q, LOG2E, ahi, alo);

    const unsigned* Bp = g_B + ((size_t)(n0 >> 4) + nw*8)*128;
    const float* sbw = sb + nw*128;
    float accA = 0.f, accB = 0.f;

    #pragma unroll
    for (int tp = 0; tp < 8; tp++) {
        uint4 B = *(const uint4*)(Bp + tp*128 + lane*4);
        float2 bb0 = *(const float2*)(sbw + tp*16 + 2*q);
        float c0 = bb0.x, c1 = bb0.y, c2 = bb0.x, c3 = bb0.y;
        mma_bf16(c0,c1,c2,c3, ahi[0],ahi[1],ahi[2],ahi[3], B.x,B.y);
        mma_bf16(c0,c1,c2,c3, alo[0],alo[1],alo[2],alo[3], B.x,B.y);
        accA += ex2_fast(c0) + ex2_fast(c1);
        accB += ex2_fast(c2) + ex2_fast(c3);
        float2 bb1 = *(const float2*)(sbw + tp*16 + 8 + 2*q);
        float d0 = bb1.x, d1 = bb1.y, d2 = bb1.x, d3 = bb1.y;
        mma_bf16(d0,d1,d2,d3, ahi[0],ahi[1],ahi[2],ahi[3], B.z,B.w);
        mma_bf16(d0,d1,d2,d3, alo[0],alo[1],alo[2],alo[3], B.z,B.w);
        accA += ex2_fast(d0) + ex2_fast(d1);
        accB += ex2_fast(d2) + ex2_fast(d3);
    }
    accA += __shfl_xor_sync(0xffffffffu, accA, 1);
    accA += __shfl_xor_sync(0xffffffffu, accA, 2);
    accB += __shfl_xor_sync(0xffffffffu, accB, 1);
    accB += __shfl_xor_sync(0xffffffffu, accB, 2);
    if (q == 0) {
        atomicAdd(&g_sum[r0],     accA);
        atomicAdd(&g_sum[r0 + 8], accB);
    }
}

// ---------------------------------------------------------------------------
// Write pass: double-buffered staging so G-1's LDS/STG overlaps G's MMA/STS.
// ---------------------------------------------------------------------------
__device__ __forceinline__ void wr_compute(
    int G, const unsigned* __restrict__ Bp, const float* __restrict__ sbw,
    float* __restrict__ tw,
    const unsigned* ahi, const unsigned* alo,
    int lane, int q, int g, int h, float nlsA, float nlsB)
{
    #pragma unroll
    for (int tpp = 0; tpp < 2; tpp++) {
        int tp = G*2 + tpp;
        uint4 B = *(const uint4*)(Bp + tp*128 + lane*4);
        #pragma unroll
        for (int hf = 0; hf < 2; hf++) {
            int t = tp*2 + hf;
            int tt = tpp*2 + hf;
            unsigned b0 = hf ? B.z : B.x;
            unsigned b1 = hf ? B.w : B.y;
            float2 bb = *(const float2*)(sbw + t*8 + 2*q);
            float c0 = bb.x, c1 = bb.y, c2 = bb.x, c3 = bb.y;
            mma_bf16(c0,c1,c2,c3, ahi[0],ahi[1],ahi[2],ahi[3], b0,b1);
            mma_bf16(c0,c1,c2,c3, alo[0],alo[1],alo[2],alo[3], b0,b1);
            int Gl = tt*2 + (q >> 1);
            int pa = Gl ^ (g & 7);
            int pb = Gl ^ ((g + 8) & 7);
            *(float2*)(tw + (g*8 + pa)*4 + h*2)     = make_float2(c0 + nlsA, c1 + nlsA);
            *(float2*)(tw + ((g+8)*8 + pb)*4 + h*2) = make_float2(c2 + nlsB, c3 + nlsB);
        }
    }
}

__device__ __forceinline__ void wr_store(
    int G, const uint4* __restrict__ buf, float* __restrict__ out,
    int rowbase, int colbase, int lane)
{
    #pragma unroll
    for (int i = 0; i < 4; i++) {
        int r = i*4 + (lane >> 3);
        int k = lane & 7;
        int p = k ^ (r & 7);
        uint4 vv = buf[r*8 + p];
        float* pd = out + (size_t)(rowbase + r)*VOCAB + colbase + G*32 + k*4;
        asm volatile("st.global.cs.v4.b32 [%0], {%1, %2, %3, %4};"
                     :: "l"(pd), "r"(vv.x), "r"(vv.y), "r"(vv.z), "r"(vv.w) : "memory");
    }
}

__global__ __launch_bounds__(256) void k_mma_write(
    const float* __restrict__ bout, float* __restrict__ out)
{
    __shared__ __align__(16) float sb[256];
    __shared__ float snls[64];
    __shared__ __align__(16) uint4 tsm[8][2][16*8];   // 32 KB double-buffered

    int tid = threadIdx.x, lane = tid & 31, warp = tid >> 5;
    int mw = warp & 3, nw = warp >> 2;
    int n0 = blockIdx.x*256;
    sb[tid] = bout[n0 + tid];
    if (tid < 64) snls[tid] = -__logf(g_sum[blockIdx.y*64 + tid]);
    __syncthreads();

    int q = lane & 3, g = lane >> 2;
    int rowbase = blockIdx.y*64 + mw*16;
    int r0 = rowbase + g;
    unsigned ahi[4], alo[4];
    build_a(r0, q, 1.0f, ahi, alo);
    float nlsA = snls[mw*16 + g], nlsB = snls[mw*16 + g + 8];

    const unsigned* Bp = g_B + ((size_t)(n0 >> 4) + nw*8)*128;
    const float* sbw = sb + nw*128;
    int colbase = n0 + nw*128;
    int h = q & 1;
    float* tw0 = (float*)tsm[warp][0];
    float* tw1 = (float*)tsm[warp][1];

    wr_compute(0, Bp, sbw, tw0, ahi, alo, lane, q, g, h, nlsA, nlsB);
    __syncwarp();
    wr_compute(1, Bp, sbw, tw1, ahi, alo, lane, q, g, h, nlsA, nlsB);
    wr_store(0, tsm[warp][0], out, rowbase, colbase, lane);
    __syncwarp();
    wr_compute(2, Bp, sbw, tw0, ahi, alo, lane, q, g, h, nlsA, nlsB);
    wr_store(1, tsm[warp][1], out, rowbase, colbase, lane);
    __syncwarp();
    wr_compute(3, Bp, sbw, tw1, ahi, alo, lane, q, g, h, nlsA, nlsB);
    wr_store(2, tsm[warp][0], out, rowbase, colbase, lane);
    __syncwarp();
    wr_store(3, tsm[warp][1], out, rowbase, colbase, lane);
}

// ---------------------------------------------------------------------------
extern "C" void kernel_launch(void* const* d_in, const int* in_sizes, int n_in,
                              void* d_out, int out_size)
{
    const int*   x    = (const int*)  d_in[0];
    const float* emb  = (const float*)d_in[1];
    const float* Wz1  = (const float*)d_in[2];  const float* bz1 = (const float*)d_in[3];
    const float* Wr1  = (const float*)d_in[4];  const float* br1 = (const float*)d_in[5];
    const float* Wh1  = (const float*)d_in[6];  const float* bh1 = (const float*)d_in[7];
    const float* Wz2  = (const float*)d_in[8];  const float* bz2 = (const float*)d_in[9];
    const float* Wr2  = (const float*)d_in[10]; const float* br2 = (const float*)d_in[11];
    const float* Wh2  = (const float*)d_in[12]; const float* bh2 = (const float*)d_in[13];
    const float* Wout = (const float*)d_in[14]; const float* bout= (const float*)d_in[15];
    float* out = (float*)d_out;

    k_pre<<<32, 256>>>(x, emb, Wz1, bz1, Wr1, br1, Wh1, bh1,
                       Wz2, bz2, Wr2, br2, Wh2, bh2);
    k_gru_prep<<<126, 256>>>(Wout, Wz1, Wr1, Wh1, Wz2, Wr2, Wh2);
    k_mma_sum  <<<dim3(VOCAB/256, NROWS/64), 256>>>(bout);
    k_mma_write<<<dim3(VOCAB/256, NROWS/64), 256>>>(bout, out);
}